// round 1
// baseline (speedup 1.0000x reference)
#include <cuda_runtime.h>
#include <cuda_bf16.h>
#include <math.h>

// Problem constants
#define Bb 8
#define Nn 512
#define Ee 256
#define Hh 8
#define HD 32
#define FFd 1024
#define TOPK 102
#define Mrows (Bb*Nn)   // 4096

// ---------------- device scratch (static globals; no runtime alloc) ----------------
__device__ unsigned int  g_adjbits[Bb*Nn*16];        // binary adjacency bitset [b*N+i][16]
__device__ unsigned char g_spd[Bb*Nn*Nn];            // spatial index 0..6
__device__ float g_qkv[Mrows*3*Ee];                  // [m][768]: q|k|v, e = h*32+d
__device__ float g_ctx[Mrows*Ee];
__device__ float g_y  [Mrows*Ee];
__device__ float g_x1 [Mrows*Ee];
__device__ float g_ff [Mrows*FFd];
__device__ float g_x2 [Mrows*Ee];

// ---------------- 1) top-k -> adjacency bitset ----------------
__global__ void topk_kernel(const float* __restrict__ adj)
{
    __shared__ unsigned long long keys[512];
    __shared__ unsigned int bw[16];
    const int row = blockIdx.x;          // b*N + i
    const int tid = threadIdx.x;         // 256 threads

    for (int j = tid; j < 512; j += 256) {
        unsigned int bits = __float_as_uint(adj[(size_t)row*512 + j]);
        unsigned int ord  = bits ^ ((bits & 0x80000000u) ? 0xFFFFFFFFu : 0x80000000u);
        keys[j] = ((unsigned long long)ord << 32) | (unsigned long long)(511 - j);
    }
    if (tid < 16) bw[tid] = 0u;
    __syncthreads();

    // bitonic sort ascending
    for (int k = 2; k <= 512; k <<= 1) {
        for (int jj = k >> 1; jj > 0; jj >>= 1) {
            for (int i = tid; i < 512; i += 256) {
                int ixj = i ^ jj;
                if (ixj > i) {
                    unsigned long long a = keys[i], c = keys[ixj];
                    bool up = ((i & k) == 0);
                    if ((a > c) == up) { keys[i] = c; keys[ixj] = a; }
                }
            }
            __syncthreads();
        }
    }
    // top-102 are keys[410..511]
    for (int t = tid; t < TOPK; t += 256) {
        int j = 511 - (int)(keys[410 + t] & 0xFFFFFFFFull);
        atomicOr(&bw[j >> 5], 1u << (j & 31));
    }
    __syncthreads();
    if (tid < 16) g_adjbits[row*16 + tid] = bw[tid];
}

// ---------------- 2) BFS (replaces Floyd-Warshall exactly for this output) ----------
__global__ void bfs_kernel()
{
    __shared__ unsigned int vis[16], fro[16], nxt[16];
    __shared__ int anyn;
    const int src = blockIdx.x;          // b*N + s
    const int b   = src >> 9;
    const int s   = src & 511;
    const int tid = threadIdx.x;         // 512 threads
    const size_t base = (size_t)src * Nn;

    g_spd[base + tid] = (tid == s) ? (unsigned char)1 : (unsigned char)0;
    if (tid < 16) {
        unsigned int m = (tid == (s >> 5)) ? (1u << (s & 31)) : 0u;
        vis[tid] = m; fro[tid] = m;
    }
    __syncthreads();

    for (int level = 1; level <= 10; level++) {
        if (tid < 16) nxt[tid] = 0u;
        if (tid == 0) anyn = 0;
        __syncthreads();

        bool active = (fro[tid >> 5] >> (tid & 31)) & 1u;
        #pragma unroll
        for (int w = 0; w < 16; w++) {
            unsigned int v = active ? g_adjbits[((size_t)(b*Nn) + tid)*16 + w] : 0u;
            unsigned int agg = __reduce_or_sync(0xFFFFFFFFu, v);
            if ((tid & 31) == 0 && agg) atomicOr(&nxt[w], agg);
        }
        __syncthreads();

        if (tid < 16) {
            unsigned int nv = nxt[tid] & ~vis[tid];
            nxt[tid] = nv;
            vis[tid] |= nv;
            if (nv) anyn = 1;
        }
        __syncthreads();
        if (!anyn) break;

        if ((nxt[tid >> 5] >> (tid & 31)) & 1u) {
            int idx = level + 1; if (idx > 6) idx = 6;
            g_spd[base + tid] = (unsigned char)idx;
        }
        if (tid < 16) fro[tid] = nxt[tid];
        __syncthreads();
    }
}

// ---------------- 3) generic tiled fp32 GEMM: C = A @ W^T + bias (+res) (relu?) -----
// A: [M][K] row-major, W: [Ndim][K] row-major, C/res: [M][Ndim]
__global__ void gemm_kernel(const float* __restrict__ A, const float* __restrict__ W,
                            const float* __restrict__ bias, const float* __restrict__ res,
                            float* __restrict__ C, int K, int Ndim, int relu)
{
    __shared__ __align__(16) float As[16][68];
    __shared__ __align__(16) float Ws[16][68];
    const int tx = threadIdx.x, ty = threadIdx.y;     // 16x16
    const int tid = ty*16 + tx;
    const int m0 = blockIdx.y * 64;
    const int n0 = blockIdx.x * 64;
    const int lc = tid & 15;
    const int lr = tid >> 4;

    float acc[4][4];
    #pragma unroll
    for (int i = 0; i < 4; i++)
        #pragma unroll
        for (int j = 0; j < 4; j++) acc[i][j] = 0.f;

    for (int k0 = 0; k0 < K; k0 += 16) {
        #pragma unroll
        for (int q = 0; q < 4; q++) {
            int r = lr + q*16;
            As[lc][r] = A[(size_t)(m0 + r)*K + k0 + lc];
            Ws[lc][r] = W[(size_t)(n0 + r)*K + k0 + lc];
        }
        __syncthreads();
        #pragma unroll
        for (int kk = 0; kk < 16; kk++) {
            float4 a = *(const float4*)&As[kk][ty*4];
            float4 w = *(const float4*)&Ws[kk][tx*4];
            float av[4] = {a.x, a.y, a.z, a.w};
            float wv[4] = {w.x, w.y, w.z, w.w};
            #pragma unroll
            for (int i = 0; i < 4; i++)
                #pragma unroll
                for (int j = 0; j < 4; j++) acc[i][j] += av[i]*wv[j];
        }
        __syncthreads();
    }

    #pragma unroll
    for (int i = 0; i < 4; i++) {
        int m = m0 + ty*4 + i;
        #pragma unroll
        for (int j = 0; j < 4; j++) {
            int n = n0 + tx*4 + j;
            float v = acc[i][j] + bias[n];
            if (res)  v += res[(size_t)m*Ndim + n];
            if (relu) v = fmaxf(v, 0.f);
            C[(size_t)m*Ndim + n] = v;
        }
    }
}

// ---------------- 4) fused masked attention (per (b,h,16-query tile)) ---------------
__global__ void attn_kernel(const float* __restrict__ emb_spd)
{
    __shared__ float qs[16][32];
    __shared__ float sc[16][512];
    __shared__ float vs[64][32];
    __shared__ unsigned int adjw[16][16];
    __shared__ float emb[8];
    __shared__ float rowinv[16];

    const int tid = threadIdx.x;             // 256
    const int qt = blockIdx.x, h = blockIdx.y, b = blockIdx.z;
    const int q0 = qt * 16;

    // loads
    {
        int e = tid;                           // 256 of 512
        #pragma unroll
        for (int u = 0; u < 2; u++, e += 256) {
            int i = e >> 5, d = e & 31;
            qs[i][d] = g_qkv[(size_t)((b*Nn + q0 + i)*768) + h*32 + d];
        }
    }
    if (tid < 7) emb[tid] = emb_spd[tid*Hh + h];
    { int i = tid >> 4, w = tid & 15;
      adjw[i][w] = g_adjbits[((size_t)(b*Nn) + q0 + i)*16 + w]; }
    __syncthreads();

    const float scale = 0.17677669529663687f;   // 1/sqrt(32)

    // scores
    #pragma unroll
    for (int rep = 0; rep < 2; rep++) {
        int j = tid + rep*256;
        float kr[32];
        const float4* kp = (const float4*)&g_qkv[(size_t)((b*Nn + j)*768) + 256 + h*32];
        #pragma unroll
        for (int q = 0; q < 8; q++) {
            float4 t = kp[q];
            kr[q*4+0]=t.x; kr[q*4+1]=t.y; kr[q*4+2]=t.z; kr[q*4+3]=t.w;
        }
        #pragma unroll
        for (int i = 0; i < 16; i++) {
            unsigned int bit = (adjw[i][j >> 5] >> (j & 31)) & 1u;
            float s;
            if (bit) {
                float dot = 0.f;
                #pragma unroll
                for (int d = 0; d < 32; d++) dot += qs[i][d]*kr[d];
                int sp = g_spd[(size_t)(b*Nn + q0 + i)*Nn + j];
                s = dot*scale + emb[sp];
            } else {
                s = -INFINITY;
            }
            sc[i][j] = s;
        }
    }
    __syncthreads();

    // softmax (unnormalized probs; keep 1/sum)
    {
        int wid = tid >> 5, lane = tid & 31;
        #pragma unroll
        for (int rr = 0; rr < 2; rr++) {
            int r = wid*2 + rr;
            float m = -INFINITY;
            for (int j = lane; j < 512; j += 32) m = fmaxf(m, sc[r][j]);
            #pragma unroll
            for (int o = 16; o; o >>= 1) m = fmaxf(m, __shfl_xor_sync(0xFFFFFFFFu, m, o));
            float e = 0.f;
            for (int j = lane; j < 512; j += 32) {
                float s = sc[r][j];
                float p = (s == -INFINITY) ? 0.f : __expf(s - m);
                sc[r][j] = p;
                e += p;
            }
            #pragma unroll
            for (int o = 16; o; o >>= 1) e += __shfl_xor_sync(0xFFFFFFFFu, e, o);
            if (lane == 0) rowinv[r] = 1.f / e;
        }
    }
    __syncthreads();

    // context
    float acc0 = 0.f, acc1 = 0.f;
    const int i0 = tid >> 5, d0 = tid & 31;
    const int i1 = i0 + 8;
    for (int kt = 0; kt < 512; kt += 64) {
        #pragma unroll
        for (int u = 0; u < 8; u++) {
            int e = tid + 256*u;
            int jj = e >> 5, d = e & 31;
            vs[jj][d] = g_qkv[(size_t)((b*Nn + kt + jj)*768) + 512 + h*32 + d];
        }
        __syncthreads();
        #pragma unroll
        for (int j = 0; j < 64; j++) {
            float v = vs[j][d0];
            acc0 += sc[i0][kt + j] * v;
            acc1 += sc[i1][kt + j] * v;
        }
        __syncthreads();
    }
    g_ctx[(size_t)((b*Nn + q0 + i0)*Ee) + h*32 + d0] = acc0 * rowinv[i0];
    g_ctx[(size_t)((b*Nn + q0 + i1)*Ee) + h*32 + d0] = acc1 * rowinv[i1];
}

// ---------------- 5) LayerNorm over rows of 256 --------------------------------------
__global__ void ln_kernel(const float* __restrict__ in, const float* __restrict__ g,
                          const float* __restrict__ be, float* __restrict__ out)
{
    __shared__ float red[16];
    const int row = blockIdx.x, tid = threadIdx.x;   // 256 threads
    float v = in[(size_t)row*Ee + tid];
    float s = v, sq = v*v;
    #pragma unroll
    for (int o = 16; o; o >>= 1) {
        s  += __shfl_xor_sync(0xFFFFFFFFu, s,  o);
        sq += __shfl_xor_sync(0xFFFFFFFFu, sq, o);
    }
    int wid = tid >> 5, lane = tid & 31;
    if (lane == 0) { red[wid] = s; red[8 + wid] = sq; }
    __syncthreads();
    if (tid == 0) {
        float ts = 0.f, tq = 0.f;
        #pragma unroll
        for (int w = 0; w < 8; w++) { ts += red[w]; tq += red[8 + w]; }
        red[0] = ts; red[8] = tq;
    }
    __syncthreads();
    float mean = red[0] * (1.f/Ee);
    float var  = red[8] * (1.f/Ee) - mean*mean;
    float rstd = rsqrtf(var + 1e-5f);
    out[(size_t)row*Ee + tid] = (v - mean) * rstd * g[tid] + be[tid];
}

// ---------------- 6) attention pooling over nodes -------------------------------------
__global__ void pool_kernel(const float* __restrict__ w_pool, const float* __restrict__ b_pool,
                            float* __restrict__ out)
{
    __shared__ float sc[512];
    __shared__ float red[16];
    __shared__ float bc[2];
    const int b = blockIdx.x, tid = threadIdx.x;     // 512 threads
    const float* row = &g_x2[(size_t)(b*Nn + tid)*Ee];

    float dot = b_pool[0];
    #pragma unroll 8
    for (int e = 0; e < Ee; e++) dot += row[e] * w_pool[e];
    float t = tanhf(dot);
    sc[tid] = t;

    int wid = tid >> 5, lane = tid & 31;
    // max
    float m = t;
    #pragma unroll
    for (int o = 16; o; o >>= 1) m = fmaxf(m, __shfl_xor_sync(0xFFFFFFFFu, m, o));
    if (lane == 0) red[wid] = m;
    __syncthreads();
    if (tid == 0) {
        float mm = -INFINITY;
        #pragma unroll
        for (int w = 0; w < 16; w++) mm = fmaxf(mm, red[w]);
        bc[0] = mm;
    }
    __syncthreads();
    float p = __expf(t - bc[0]);
    sc[tid] = p;
    float s = p;
    #pragma unroll
    for (int o = 16; o; o >>= 1) s += __shfl_xor_sync(0xFFFFFFFFu, s, o);
    if (lane == 0) red[wid] = s;
    __syncthreads();
    if (tid == 0) {
        float ss = 0.f;
        #pragma unroll
        for (int w = 0; w < 16; w++) ss += red[w];
        bc[1] = ss;
    }
    __syncthreads();

    if (tid < Ee) {
        float acc = 0.f;
        float inv = 1.f / bc[1];
        for (int n = 0; n < Nn; n++)
            acc += g_x2[(size_t)(b*Nn + n)*Ee + tid] * sc[n];
        out[(size_t)b*Ee + tid] = acc * inv;
    }
}

// ---------------- launch -------------------------------------------------------------
extern "C" void kernel_launch(void* const* d_in, const int* in_sizes, int n_in,
                              void* d_out, int out_size)
{
    const float* x       = (const float*)d_in[0];
    const float* adj     = (const float*)d_in[1];
    const float* emb_spd = (const float*)d_in[2];
    const float* w_qkv   = (const float*)d_in[3];
    const float* b_qkv   = (const float*)d_in[4];
    const float* w_out   = (const float*)d_in[5];
    const float* b_out   = (const float*)d_in[6];
    const float* w_ff1   = (const float*)d_in[7];
    const float* b_ff1   = (const float*)d_in[8];
    const float* w_ff2   = (const float*)d_in[9];
    const float* b_ff2   = (const float*)d_in[10];
    const float* g1      = (const float*)d_in[11];
    const float* beta1   = (const float*)d_in[12];
    const float* g2      = (const float*)d_in[13];
    const float* beta2   = (const float*)d_in[14];
    const float* w_pool  = (const float*)d_in[15];
    const float* b_pool  = (const float*)d_in[16];
    float* out = (float*)d_out;

    float* p_qkv; cudaGetSymbolAddress((void**)&p_qkv, g_qkv);
    float* p_ctx; cudaGetSymbolAddress((void**)&p_ctx, g_ctx);
    float* p_y;   cudaGetSymbolAddress((void**)&p_y,   g_y);
    float* p_x1;  cudaGetSymbolAddress((void**)&p_x1,  g_x1);
    float* p_ff;  cudaGetSymbolAddress((void**)&p_ff,  g_ff);
    float* p_x2;  cudaGetSymbolAddress((void**)&p_x2,  g_x2);

    dim3 tb(16, 16);

    // 1) top-k -> adjacency bits
    topk_kernel<<<Bb*Nn, 256>>>(adj);
    // 2) BFS shortest-path index
    bfs_kernel<<<Bb*Nn, 512>>>();
    // 3) QKV projection
    gemm_kernel<<<dim3(768/64, Mrows/64), tb>>>(x, w_qkv, b_qkv, nullptr, p_qkv, 256, 768, 0);
    // 4) attention
    attn_kernel<<<dim3(Nn/16, Hh, Bb), 256>>>(emb_spd);
    // 5) out projection + residual
    gemm_kernel<<<dim3(Ee/64, Mrows/64), tb>>>(p_ctx, w_out, b_out, x, p_y, 256, Ee, 0);
    // 6) LN1
    ln_kernel<<<Mrows, 256>>>(p_y, g1, beta1, p_x1);
    // 7) FF1 + relu
    gemm_kernel<<<dim3(FFd/64, Mrows/64), tb>>>(p_x1, w_ff1, b_ff1, nullptr, p_ff, 256, FFd, 1);
    // 8) FF2 + residual
    gemm_kernel<<<dim3(Ee/64, Mrows/64), tb>>>(p_ff, w_ff2, b_ff2, p_x1, p_y, 1024, Ee, 0);
    // 9) LN2
    ln_kernel<<<Mrows, 256>>>(p_y, g2, beta2, p_x2);
    // 10) pooling
    pool_kernel<<<Bb, 512>>>(w_pool, b_pool, out);

    (void)in_sizes; (void)n_in; (void)out_size;
}

// round 3
// speedup vs baseline: 1.0425x; 1.0425x over previous
#include <cuda_runtime.h>
#include <cuda_bf16.h>
#include <mma.h>
#include <math.h>
#include <stdint.h>

using namespace nvcuda;

// Problem constants
#define Bb 8
#define Nn 512
#define Ee 256
#define Hh 8
#define HD 32
#define FFd 1024
#define TOPK 102
#define Mrows (Bb*Nn)   // 4096

// ---------------- device scratch ----------------
__device__ unsigned int  g_adjbits[Bb*Nn*16];
__device__ unsigned char g_spd[Bb*Nn*Nn];
__device__ float g_qkv[Mrows*3*Ee];
__device__ float g_ctx[Mrows*Ee];
__device__ float g_y  [Mrows*Ee];
__device__ float g_x1 [Mrows*Ee];
__device__ float g_ff [Mrows*FFd];
__device__ float g_x2 [Mrows*Ee];

// split-bf16 operand buffers
__device__ __nv_bfloat16 g_xh  [Mrows*Ee],  g_xl  [Mrows*Ee];
__device__ __nv_bfloat16 g_ctxh[Mrows*Ee],  g_ctxl[Mrows*Ee];
__device__ __nv_bfloat16 g_x1h [Mrows*Ee],  g_x1l [Mrows*Ee];
__device__ __nv_bfloat16 g_ffh [Mrows*FFd], g_ffl [Mrows*FFd];
__device__ __nv_bfloat16 g_wqkvh[768*256],  g_wqkvl[768*256];
__device__ __nv_bfloat16 g_wouth[256*256],  g_woutl[256*256];
__device__ __nv_bfloat16 g_wff1h[1024*256], g_wff1l[1024*256];
__device__ __nv_bfloat16 g_wff2h[256*1024], g_wff2l[256*1024];

// ---------------- 0) fp32 -> (hi, lo) bf16 split ----------------
__global__ void cvt_split(const float* __restrict__ in, __nv_bfloat16* __restrict__ hi,
                          __nv_bfloat16* __restrict__ lo, int n)
{
    int i = (blockIdx.x*blockDim.x + threadIdx.x) * 4;
    if (i >= n) return;
    float4 v = *(const float4*)(in + i);
    __nv_bfloat162 h0 = __floats2bfloat162_rn(v.x, v.y);
    __nv_bfloat162 h1 = __floats2bfloat162_rn(v.z, v.w);
    __nv_bfloat162 l0 = __floats2bfloat162_rn(v.x - __bfloat162float(h0.x),
                                              v.y - __bfloat162float(h0.y));
    __nv_bfloat162 l1 = __floats2bfloat162_rn(v.z - __bfloat162float(h1.x),
                                              v.w - __bfloat162float(h1.y));
    *(__nv_bfloat162*)(hi + i)     = h0;
    *(__nv_bfloat162*)(hi + i + 2) = h1;
    *(__nv_bfloat162*)(lo + i)     = l0;
    *(__nv_bfloat162*)(lo + i + 2) = l1;
}

// ---------------- 1) top-k -> adjacency bitset ----------------
__global__ void topk_kernel(const float* __restrict__ adj)
{
    __shared__ unsigned long long keys[512];
    __shared__ unsigned int bw[16];
    const int row = blockIdx.x;
    const int tid = threadIdx.x;

    for (int j = tid; j < 512; j += 256) {
        unsigned int bits = __float_as_uint(adj[(size_t)row*512 + j]);
        unsigned int ord  = bits ^ ((bits & 0x80000000u) ? 0xFFFFFFFFu : 0x80000000u);
        keys[j] = ((unsigned long long)ord << 32) | (unsigned long long)(511 - j);
    }
    if (tid < 16) bw[tid] = 0u;
    __syncthreads();

    for (int k = 2; k <= 512; k <<= 1) {
        for (int jj = k >> 1; jj > 0; jj >>= 1) {
            for (int i = tid; i < 512; i += 256) {
                int ixj = i ^ jj;
                if (ixj > i) {
                    unsigned long long a = keys[i], c = keys[ixj];
                    bool up = ((i & k) == 0);
                    if ((a > c) == up) { keys[i] = c; keys[ixj] = a; }
                }
            }
            __syncthreads();
        }
    }
    for (int t = tid; t < TOPK; t += 256) {
        int j = 511 - (int)(keys[410 + t] & 0xFFFFFFFFull);
        atomicOr(&bw[j >> 5], 1u << (j & 31));
    }
    __syncthreads();
    if (tid < 16) g_adjbits[row*16 + tid] = bw[tid];
}

// ---------------- 2) BFS (exact replacement of FW for this output) ----------------
__global__ void bfs_kernel()
{
    __shared__ unsigned int vis[16], fro[16], nxt[16];
    __shared__ int anyn;
    const int src = blockIdx.x;
    const int b   = src >> 9;
    const int s   = src & 511;
    const int tid = threadIdx.x;
    const size_t base = (size_t)src * Nn;

    g_spd[base + tid] = (tid == s) ? (unsigned char)1 : (unsigned char)0;
    if (tid < 16) {
        unsigned int m = (tid == (s >> 5)) ? (1u << (s & 31)) : 0u;
        vis[tid] = m; fro[tid] = m;
    }
    __syncthreads();

    for (int level = 1; level <= 10; level++) {
        if (tid < 16) nxt[tid] = 0u;
        if (tid == 0) anyn = 0;
        __syncthreads();

        bool active = (fro[tid >> 5] >> (tid & 31)) & 1u;
        #pragma unroll
        for (int w = 0; w < 16; w++) {
            unsigned int v = active ? g_adjbits[((size_t)(b*Nn) + tid)*16 + w] : 0u;
            unsigned int agg = __reduce_or_sync(0xFFFFFFFFu, v);
            if ((tid & 31) == 0 && agg) atomicOr(&nxt[w], agg);
        }
        __syncthreads();

        if (tid < 16) {
            unsigned int nv = nxt[tid] & ~vis[tid];
            nxt[tid] = nv;
            vis[tid] |= nv;
            if (nv) anyn = 1;
        }
        __syncthreads();
        if (!anyn) break;

        if ((nxt[tid >> 5] >> (tid & 31)) & 1u) {
            int idx = level + 1; if (idx > 6) idx = 6;
            g_spd[base + tid] = (unsigned char)idx;
        }
        if (tid < 16) fro[tid] = nxt[tid];
        __syncthreads();
    }
}

// ---------------- 3) split-bf16 wmma GEMM: C = A@W^T + bias (+res)(relu) ------------
// Ah/Al: [M][K] bf16, Wh/Wl: [Ndim][K] bf16.  Block tile 128x128, k-chunk 32.
// 8 warps: 2 (rows of 64) x 4 (cols of 32); per warp 4x2 16x16 fragments.
// smem: AHs/ALs/WHs/WLs [128][48] bf16 (12288B each), epi [8][16][40] f32 (20480B)
#define GEMM_SMEM (4*128*48*2 + 8*16*40*4)
__global__ void __launch_bounds__(256) gemm_wmma(
    const __nv_bfloat16* __restrict__ Ah, const __nv_bfloat16* __restrict__ Al,
    const __nv_bfloat16* __restrict__ Wh, const __nv_bfloat16* __restrict__ Wl,
    const float* __restrict__ bias, const float* __restrict__ res,
    float* __restrict__ C, int K, int Ndim, int relu)
{
    extern __shared__ __align__(128) char s[];
    __nv_bfloat16* AHs = (__nv_bfloat16*)s;              // [128][48]
    __nv_bfloat16* ALs = AHs + 128*48;
    __nv_bfloat16* WHs = ALs + 128*48;
    __nv_bfloat16* WLs = WHs + 128*48;
    float* epi = (float*)(s + 4*128*48*2);               // [8][16][40]

    const int tid = threadIdx.x, wid = tid >> 5, lane = tid & 31;
    const int m0 = blockIdx.y * 128, n0 = blockIdx.x * 128;
    const int wr = wid >> 2, wc = wid & 3;

    wmma::fragment<wmma::accumulator,16,16,16,float> acc[4][2];
    #pragma unroll
    for (int rt = 0; rt < 4; rt++)
        #pragma unroll
        for (int ct = 0; ct < 2; ct++) wmma::fill_fragment(acc[rt][ct], 0.f);

    const int r  = tid >> 1;          // 0..127
    const int cs = (tid & 1) * 16;    // 0 or 16

    for (int k0 = 0; k0 < K; k0 += 32) {
        const size_t aoff = (size_t)(m0 + r)*K + k0 + cs;
        const size_t woff = (size_t)(n0 + r)*K + k0 + cs;
        {
            uint4 t0 = *(const uint4*)(Ah + aoff);
            uint4 t1 = *(const uint4*)(Ah + aoff + 8);
            *(uint4*)(AHs + r*48 + cs)     = t0;
            *(uint4*)(AHs + r*48 + cs + 8) = t1;
            t0 = *(const uint4*)(Al + aoff);
            t1 = *(const uint4*)(Al + aoff + 8);
            *(uint4*)(ALs + r*48 + cs)     = t0;
            *(uint4*)(ALs + r*48 + cs + 8) = t1;
            t0 = *(const uint4*)(Wh + woff);
            t1 = *(const uint4*)(Wh + woff + 8);
            *(uint4*)(WHs + r*48 + cs)     = t0;
            *(uint4*)(WHs + r*48 + cs + 8) = t1;
            t0 = *(const uint4*)(Wl + woff);
            t1 = *(const uint4*)(Wl + woff + 8);
            *(uint4*)(WLs + r*48 + cs)     = t0;
            *(uint4*)(WLs + r*48 + cs + 8) = t1;
        }
        __syncthreads();

        #pragma unroll
        for (int ks = 0; ks < 2; ks++) {
            wmma::fragment<wmma::matrix_a,16,16,16,__nv_bfloat16,wmma::row_major> ah[4], al[4];
            wmma::fragment<wmma::matrix_b,16,16,16,__nv_bfloat16,wmma::col_major> bh[2], bl[2];
            #pragma unroll
            for (int rt = 0; rt < 4; rt++) {
                const int ro = (wr*64 + rt*16)*48 + ks*16;
                wmma::load_matrix_sync(ah[rt], AHs + ro, 48);
                wmma::load_matrix_sync(al[rt], ALs + ro, 48);
            }
            #pragma unroll
            for (int ct = 0; ct < 2; ct++) {
                const int co = (wc*32 + ct*16)*48 + ks*16;
                wmma::load_matrix_sync(bh[ct], WHs + co, 48);
                wmma::load_matrix_sync(bl[ct], WLs + co, 48);
            }
            #pragma unroll
            for (int rt = 0; rt < 4; rt++)
                #pragma unroll
                for (int ct = 0; ct < 2; ct++) {
                    wmma::mma_sync(acc[rt][ct], ah[rt], bh[ct], acc[rt][ct]);
                    wmma::mma_sync(acc[rt][ct], ah[rt], bl[ct], acc[rt][ct]);
                    wmma::mma_sync(acc[rt][ct], al[rt], bh[ct], acc[rt][ct]);
                }
        }
        __syncthreads();
    }

    // epilogue
    float* ep = epi + wid*16*40;
    const int rr = lane & 15, hf = lane >> 4;
    #pragma unroll
    for (int rt = 0; rt < 4; rt++) {
        wmma::store_matrix_sync(ep,      acc[rt][0], 40, wmma::mem_row_major);
        wmma::store_matrix_sync(ep + 16, acc[rt][1], 40, wmma::mem_row_major);
        __syncwarp();
        const int m = m0 + wr*64 + rt*16 + rr;
        #pragma unroll
        for (int q = 0; q < 4; q++) {
            const int n = n0 + wc*32 + hf*16 + q*4;
            float4 v = *(float4*)&ep[rr*40 + hf*16 + q*4];
            float4 bv = *(const float4*)&bias[n];
            v.x += bv.x; v.y += bv.y; v.z += bv.z; v.w += bv.w;
            if (res) {
                float4 rv = *(const float4*)&res[(size_t)m*Ndim + n];
                v.x += rv.x; v.y += rv.y; v.z += rv.z; v.w += rv.w;
            }
            if (relu) {
                v.x = fmaxf(v.x, 0.f); v.y = fmaxf(v.y, 0.f);
                v.z = fmaxf(v.z, 0.f); v.w = fmaxf(v.w, 0.f);
            }
            *(float4*)&C[(size_t)m*Ndim + n] = v;
        }
        __syncwarp();
    }
}

// ---------------- 4) fused masked attention: 32 queries/block, register-tiled -------
#define AT_SMEM 81056
__global__ void __launch_bounds__(256, 2) attn_kernel(const float* __restrict__ emb_spd)
{
    extern __shared__ __align__(16) char asmem[];
    float* scf        = (float*)asmem;                   // [32][512]
    float* kvf        = (float*)(asmem + 65536);         // [32][68]
    float* qtf        = (float*)(asmem + 74240);         // [32][36]
    unsigned int* adjs = (unsigned int*)(asmem + 78848); // [32][16]
    float* embs       = (float*)(asmem + 80896);
    float* rinv       = (float*)(asmem + 80928);

    const int tid = threadIdx.x;                 // 256
    const int lane = tid & 31, w8 = tid >> 5;    // 8 warps
    const int qt = blockIdx.x, h = blockIdx.y, b = blockIdx.z;
    const int q0 = qt * 32;
    const float scale = 0.17677669529663687f;    // 1/sqrt(32)

    #pragma unroll
    for (int p = 0; p < 4; p++) {
        int i = w8 + p*8;
        qtf[lane*36 + i] = g_qkv[(size_t)(b*Nn + q0 + i)*768 + h*32 + lane];
    }
    for (int idx = tid; idx < 512; idx += 256) {
        int r = idx >> 4, w = idx & 15;
        adjs[idx] = g_adjbits[((size_t)(b*Nn) + q0 + r)*16 + w];
    }
    if (tid < 7) embs[tid] = emb_spd[tid*Hh + h];
    __syncthreads();

    // ---- scores ----
    const int qg = tid >> 4, jg = tid & 15;
    for (int jc = 0; jc < 8; jc++) {
        const int j0 = jc * 64;
        #pragma unroll
        for (int p = 0; p < 8; p++) {
            int j = w8 + p*8;
            kvf[lane*68 + j] = g_qkv[(size_t)(b*Nn + j0 + j)*768 + 256 + h*32 + lane];
        }
        __syncthreads();

        float4 a0 = {0,0,0,0}, a1 = {0,0,0,0};
        #pragma unroll
        for (int d = 0; d < 32; d++) {
            float2 q2 = *(float2*)&qtf[d*36 + qg*2];
            float4 k4 = *(float4*)&kvf[d*68 + jg*4];
            a0.x += q2.x*k4.x; a0.y += q2.x*k4.y; a0.z += q2.x*k4.z; a0.w += q2.x*k4.w;
            a1.x += q2.y*k4.x; a1.y += q2.y*k4.y; a1.z += q2.y*k4.z; a1.w += q2.y*k4.w;
        }
        const int jb = j0 + jg*4;
        #pragma unroll
        for (int qq = 0; qq < 2; qq++) {
            const int i = qg*2 + qq;
            float4 a = qq ? a1 : a0;
            unsigned int spw = *(const unsigned int*)&g_spd[(size_t)(b*Nn + q0 + i)*Nn + jb];
            unsigned int aw = adjs[i*16 + (jb >> 5)] >> (jb & 31);
            float4 o;
            o.x = (aw & 1u)      ? a.x*scale + embs[ spw        & 255u] : -INFINITY;
            o.y = ((aw>>1) & 1u) ? a.y*scale + embs[(spw >> 8)  & 255u] : -INFINITY;
            o.z = ((aw>>2) & 1u) ? a.z*scale + embs[(spw >> 16) & 255u] : -INFINITY;
            o.w = ((aw>>3) & 1u) ? a.w*scale + embs[(spw >> 24) & 255u] : -INFINITY;
            *(float4*)&scf[i*512 + jb] = o;
        }
        __syncthreads();
    }

    // ---- softmax ----
    #pragma unroll
    for (int rr = 0; rr < 4; rr++) {
        const int r = w8*4 + rr;
        float m = -INFINITY;
        for (int j = lane; j < 512; j += 32) m = fmaxf(m, scf[r*512 + j]);
        #pragma unroll
        for (int o = 16; o; o >>= 1) m = fmaxf(m, __shfl_xor_sync(0xFFFFFFFFu, m, o));
        float e = 0.f;
        for (int j = lane; j < 512; j += 32) {
            float s = scf[r*512 + j];
            float p = (s == -INFINITY) ? 0.f : __expf(s - m);
            scf[r*512 + j] = p;
            e += p;
        }
        #pragma unroll
        for (int o = 16; o; o >>= 1) e += __shfl_xor_sync(0xFFFFFFFFu, e, o);
        if (lane == 0) rinv[r] = 1.f / e;
    }
    __syncthreads();

    // ---- AV ----
    float o0 = 0.f, o1 = 0.f, o2 = 0.f, o3 = 0.f;
    for (int jc = 0; jc < 8; jc++) {
        const int j0 = jc * 64;
        #pragma unroll
        for (int p = 0; p < 8; p++) {
            int j = w8 + p*8;
            kvf[lane*68 + j] = g_qkv[(size_t)(b*Nn + j0 + j)*768 + 512 + h*32 + lane];
        }
        __syncthreads();
        #pragma unroll
        for (int jq = 0; jq < 16; jq++) {
            float4 vv = *(float4*)&kvf[lane*68 + jq*4];
            float4 s0 = *(float4*)&scf[(w8*4+0)*512 + j0 + jq*4];
            float4 s1 = *(float4*)&scf[(w8*4+1)*512 + j0 + jq*4];
            float4 s2 = *(float4*)&scf[(w8*4+2)*512 + j0 + jq*4];
            float4 s3 = *(float4*)&scf[(w8*4+3)*512 + j0 + jq*4];
            o0 += s0.x*vv.x + s0.y*vv.y + s0.z*vv.z + s0.w*vv.w;
            o1 += s1.x*vv.x + s1.y*vv.y + s1.z*vv.z + s1.w*vv.w;
            o2 += s2.x*vv.x + s2.y*vv.y + s2.z*vv.z + s2.w*vv.w;
            o3 += s3.x*vv.x + s3.y*vv.y + s3.z*vv.z + s3.w*vv.w;
        }
        __syncthreads();
    }
    {
        const int d = lane;
        g_ctx[(size_t)(b*Nn + q0 + w8*4 + 0)*Ee + h*32 + d] = o0 * rinv[w8*4+0];
        g_ctx[(size_t)(b*Nn + q0 + w8*4 + 1)*Ee + h*32 + d] = o1 * rinv[w8*4+1];
        g_ctx[(size_t)(b*Nn + q0 + w8*4 + 2)*Ee + h*32 + d] = o2 * rinv[w8*4+2];
        g_ctx[(size_t)(b*Nn + q0 + w8*4 + 3)*Ee + h*32 + d] = o3 * rinv[w8*4+3];
    }
}

// ---------------- 5) LayerNorm ----------------
__global__ void ln_kernel(const float* __restrict__ in, const float* __restrict__ g,
                          const float* __restrict__ be, float* __restrict__ out)
{
    __shared__ float red[16];
    const int row = blockIdx.x, tid = threadIdx.x;
    float v = in[(size_t)row*Ee + tid];
    float s = v, sq = v*v;
    #pragma unroll
    for (int o = 16; o; o >>= 1) {
        s  += __shfl_xor_sync(0xFFFFFFFFu, s,  o);
        sq += __shfl_xor_sync(0xFFFFFFFFu, sq, o);
    }
    int wid = tid >> 5, lane = tid & 31;
    if (lane == 0) { red[wid] = s; red[8 + wid] = sq; }
    __syncthreads();
    if (tid == 0) {
        float ts = 0.f, tq = 0.f;
        #pragma unroll
        for (int w = 0; w < 8; w++) { ts += red[w]; tq += red[8 + w]; }
        red[0] = ts; red[8] = tq;
    }
    __syncthreads();
    float mean = red[0] * (1.f/Ee);
    float var  = red[8] * (1.f/Ee) - mean*mean;
    float rstd = rsqrtf(var + 1e-5f);
    out[(size_t)row*Ee + tid] = (v - mean) * rstd * g[tid] + be[tid];
}

// ---------------- 6) attention pooling ----------------
__global__ void pool_kernel(const float* __restrict__ w_pool, const float* __restrict__ b_pool,
                            float* __restrict__ out)
{
    __shared__ float sc[512];
    __shared__ float red[16];
    __shared__ float bc[2];
    const int b = blockIdx.x, tid = threadIdx.x;
    const float* row = &g_x2[(size_t)(b*Nn + tid)*Ee];

    float dot = b_pool[0];
    #pragma unroll 8
    for (int e = 0; e < Ee; e++) dot += row[e] * w_pool[e];
    float t = tanhf(dot);
    sc[tid] = t;

    int wid = tid >> 5, lane = tid & 31;
    float m = t;
    #pragma unroll
    for (int o = 16; o; o >>= 1) m = fmaxf(m, __shfl_xor_sync(0xFFFFFFFFu, m, o));
    if (lane == 0) red[wid] = m;
    __syncthreads();
    if (tid == 0) {
        float mm = -INFINITY;
        #pragma unroll
        for (int w = 0; w < 16; w++) mm = fmaxf(mm, red[w]);
        bc[0] = mm;
    }
    __syncthreads();
    float p = __expf(t - bc[0]);
    sc[tid] = p;
    float s = p;
    #pragma unroll
    for (int o = 16; o; o >>= 1) s += __shfl_xor_sync(0xFFFFFFFFu, s, o);
    if (lane == 0) red[wid] = s;
    __syncthreads();
    if (tid == 0) {
        float ss = 0.f;
        #pragma unroll
        for (int w = 0; w < 16; w++) ss += red[w];
        bc[1] = ss;
    }
    __syncthreads();

    if (tid < Ee) {
        float acc = 0.f;
        float inv = 1.f / bc[1];
        for (int n = 0; n < Nn; n++)
            acc += g_x2[(size_t)(b*Nn + n)*Ee + tid] * sc[n];
        out[(size_t)b*Ee + tid] = acc * inv;
    }
}

// ---------------- launch ----------------
extern "C" void kernel_launch(void* const* d_in, const int* in_sizes, int n_in,
                              void* d_out, int out_size)
{
    const float* x       = (const float*)d_in[0];
    const float* adj     = (const float*)d_in[1];
    const float* emb_spd = (const float*)d_in[2];
    const float* w_qkv   = (const float*)d_in[3];
    const float* b_qkv   = (const float*)d_in[4];
    const float* w_out   = (const float*)d_in[5];
    const float* b_out   = (const float*)d_in[6];
    const float* w_ff1   = (const float*)d_in[7];
    const float* b_ff1   = (const float*)d_in[8];
    const float* w_ff2   = (const float*)d_in[9];
    const float* b_ff2   = (const float*)d_in[10];
    const float* g1      = (const float*)d_in[11];
    const float* beta1   = (const float*)d_in[12];
    const float* g2      = (const float*)d_in[13];
    const float* beta2   = (const float*)d_in[14];
    const float* w_pool  = (const float*)d_in[15];
    const float* b_pool  = (const float*)d_in[16];
    float* out = (float*)d_out;

    float* p_qkv; cudaGetSymbolAddress((void**)&p_qkv, g_qkv);
    float* p_ctx; cudaGetSymbolAddress((void**)&p_ctx, g_ctx);
    float* p_y;   cudaGetSymbolAddress((void**)&p_y,   g_y);
    float* p_x1;  cudaGetSymbolAddress((void**)&p_x1,  g_x1);
    float* p_ff;  cudaGetSymbolAddress((void**)&p_ff,  g_ff);
    float* p_x2;  cudaGetSymbolAddress((void**)&p_x2,  g_x2);

    __nv_bfloat16 *xh, *xl, *ctxh, *ctxl, *x1h, *x1l, *ffh, *ffl;
    __nv_bfloat16 *wqkvh, *wqkvl, *wouth, *woutl, *wff1h, *wff1l, *wff2h, *wff2l;
    cudaGetSymbolAddress((void**)&xh, g_xh);     cudaGetSymbolAddress((void**)&xl, g_xl);
    cudaGetSymbolAddress((void**)&ctxh, g_ctxh); cudaGetSymbolAddress((void**)&ctxl, g_ctxl);
    cudaGetSymbolAddress((void**)&x1h, g_x1h);   cudaGetSymbolAddress((void**)&x1l, g_x1l);
    cudaGetSymbolAddress((void**)&ffh, g_ffh);   cudaGetSymbolAddress((void**)&ffl, g_ffl);
    cudaGetSymbolAddress((void**)&wqkvh, g_wqkvh); cudaGetSymbolAddress((void**)&wqkvl, g_wqkvl);
    cudaGetSymbolAddress((void**)&wouth, g_wouth); cudaGetSymbolAddress((void**)&woutl, g_woutl);
    cudaGetSymbolAddress((void**)&wff1h, g_wff1h); cudaGetSymbolAddress((void**)&wff1l, g_wff1l);
    cudaGetSymbolAddress((void**)&wff2h, g_wff2h); cudaGetSymbolAddress((void**)&wff2l, g_wff2l);

    cudaFuncSetAttribute(gemm_wmma,  cudaFuncAttributeMaxDynamicSharedMemorySize, GEMM_SMEM);
    cudaFuncSetAttribute(attn_kernel, cudaFuncAttributeMaxDynamicSharedMemorySize, AT_SMEM);

    // graph/topology path
    topk_kernel<<<Bb*Nn, 256>>>(adj);
    bfs_kernel<<<Bb*Nn, 512>>>();

    // operand splits (weights + x)
    cvt_split<<<(Mrows*Ee)/1024, 256>>>(x, xh, xl, Mrows*Ee);
    cvt_split<<<(768*256)/1024, 256>>>(w_qkv, wqkvh, wqkvl, 768*256);
    cvt_split<<<(256*256)/1024, 256>>>(w_out, wouth, woutl, 256*256);
    cvt_split<<<(1024*256)/1024, 256>>>(w_ff1, wff1h, wff1l, 1024*256);
    cvt_split<<<(256*1024)/1024, 256>>>(w_ff2, wff2h, wff2l, 256*1024);

    // QKV projection
    gemm_wmma<<<dim3(6, 32), 256, GEMM_SMEM>>>(xh, xl, wqkvh, wqkvl, b_qkv, nullptr, p_qkv, 256, 768, 0);
    // attention
    attn_kernel<<<dim3(16, 8, 8), 256, AT_SMEM>>>(emb_spd);
    cvt_split<<<(Mrows*Ee)/1024, 256>>>(p_ctx, ctxh, ctxl, Mrows*Ee);
    // out projection + residual
    gemm_wmma<<<dim3(2, 32), 256, GEMM_SMEM>>>(ctxh, ctxl, wouth, woutl, b_out, x, p_y, 256, 256, 0);
    // LN1
    ln_kernel<<<Mrows, 256>>>(p_y, g1, beta1, p_x1);
    cvt_split<<<(Mrows*Ee)/1024, 256>>>(p_x1, x1h, x1l, Mrows*Ee);
    // FF1 + relu
    gemm_wmma<<<dim3(8, 32), 256, GEMM_SMEM>>>(x1h, x1l, wff1h, wff1l, b_ff1, nullptr, p_ff, 256, 1024, 1);
    cvt_split<<<(Mrows*FFd)/1024, 256>>>(p_ff, ffh, ffl, Mrows*FFd);
    // FF2 + residual
    gemm_wmma<<<dim3(2, 32), 256, GEMM_SMEM>>>(ffh, ffl, wff2h, wff2l, b_ff2, p_x1, p_y, 1024, 256, 0);
    // LN2
    ln_kernel<<<Mrows, 256>>>(p_y, g2, beta2, p_x2);
    // pooling
    pool_kernel<<<Bb, 512>>>(w_pool, b_pool, out);

    (void)in_sizes; (void)n_in; (void)out_size;
}

// round 4
// speedup vs baseline: 1.0461x; 1.0034x over previous
#include <cuda_runtime.h>
#include <cuda_bf16.h>
#include <mma.h>
#include <math.h>
#include <stdint.h>

using namespace nvcuda;

// Problem constants
#define Bb 8
#define Nn 512
#define Ee 256
#define Hh 8
#define HD 32
#define FFd 1024
#define TOPK 102
#define Mrows (Bb*Nn)   // 4096

// ---------------- device scratch ----------------
__device__ unsigned int  g_adjbits[Bb*Nn*16];
__device__ unsigned char g_spd[Bb*Nn*Nn];
__device__ __align__(16) float g_qkv[Mrows*3*Ee];
__device__ __align__(16) float g_y  [Mrows*Ee];
__device__ __align__(16) float g_x1 [Mrows*Ee];
__device__ __align__(16) float g_x2 [Mrows*Ee];

// split-bf16 operand buffers
__device__ __align__(16) __nv_bfloat16 g_xh  [Mrows*Ee],  g_xl  [Mrows*Ee];
__device__ __align__(16) __nv_bfloat16 g_ctxh[Mrows*Ee],  g_ctxl[Mrows*Ee];
__device__ __align__(16) __nv_bfloat16 g_x1h [Mrows*Ee],  g_x1l [Mrows*Ee];
__device__ __align__(16) __nv_bfloat16 g_ffh [Mrows*FFd], g_ffl [Mrows*FFd];
__device__ __align__(16) __nv_bfloat16 g_wqkvh[768*256],  g_wqkvl[768*256];
__device__ __align__(16) __nv_bfloat16 g_wouth[256*256],  g_woutl[256*256];
__device__ __align__(16) __nv_bfloat16 g_wff1h[1024*256], g_wff1l[1024*256];
__device__ __align__(16) __nv_bfloat16 g_wff2h[256*1024], g_wff2l[256*1024];

// ================= helpers =================
__device__ __forceinline__ uint32_t smem_to_u32(const void* p) {
    uint32_t a;
    asm("{ .reg .u64 t; cvta.to.shared.u64 t, %1; cvt.u32.u64 %0, t; }" : "=r"(a) : "l"(p));
    return a;
}
__device__ __forceinline__ void cpasync16(uint32_t sm, const void* g) {
    asm volatile("cp.async.cg.shared.global [%0], [%1], 16;" :: "r"(sm), "l"(g) : "memory");
}
__device__ __forceinline__ void split2(float a, float b, __nv_bfloat162& h, __nv_bfloat162& l) {
    h = __floats2bfloat162_rn(a, b);
    l = __floats2bfloat162_rn(a - __bfloat162float(h.x), b - __bfloat162float(h.y));
}

// ---------------- 0) fused fp32 -> (hi, lo) bf16 split for all static operands ------
__global__ void cvt_all(const float* __restrict__ x, const float* __restrict__ wqkv,
                        const float* __restrict__ wout, const float* __restrict__ wff1,
                        const float* __restrict__ wff2)
{
    int gid = blockIdx.x*256 + threadIdx.x;       // float4 index, total 458752
    const float* in; __nv_bfloat16 *hi, *lo; int off;
    if      (gid < 262144) { in = x;    hi = g_xh;    lo = g_xl;    off = gid; }
    else if (gid < 311296) { in = wqkv; hi = g_wqkvh; lo = g_wqkvl; off = gid - 262144; }
    else if (gid < 327680) { in = wout; hi = g_wouth; lo = g_woutl; off = gid - 311296; }
    else if (gid < 393216) { in = wff1; hi = g_wff1h; lo = g_wff1l; off = gid - 327680; }
    else                   { in = wff2; hi = g_wff2h; lo = g_wff2l; off = gid - 393216; }
    float4 v = ((const float4*)in)[off];
    __nv_bfloat162 h0, l0, h1, l1;
    split2(v.x, v.y, h0, l0);
    split2(v.z, v.w, h1, l1);
    int i = off*4;
    *(__nv_bfloat162*)(hi + i)     = h0;
    *(__nv_bfloat162*)(hi + i + 2) = h1;
    *(__nv_bfloat162*)(lo + i)     = l0;
    *(__nv_bfloat162*)(lo + i + 2) = l1;
}

// ---------------- 1) top-k -> adjacency bitset ----------------
__global__ void topk_kernel(const float* __restrict__ adj)
{
    __shared__ unsigned long long keys[512];
    __shared__ unsigned int bw[16];
    const int row = blockIdx.x;
    const int tid = threadIdx.x;

    for (int j = tid; j < 512; j += 256) {
        unsigned int bits = __float_as_uint(adj[(size_t)row*512 + j]);
        unsigned int ord  = bits ^ ((bits & 0x80000000u) ? 0xFFFFFFFFu : 0x80000000u);
        keys[j] = ((unsigned long long)ord << 32) | (unsigned long long)(511 - j);
    }
    if (tid < 16) bw[tid] = 0u;
    __syncthreads();

    for (int k = 2; k <= 512; k <<= 1) {
        for (int jj = k >> 1; jj > 0; jj >>= 1) {
            for (int i = tid; i < 512; i += 256) {
                int ixj = i ^ jj;
                if (ixj > i) {
                    unsigned long long a = keys[i], c = keys[ixj];
                    bool up = ((i & k) == 0);
                    if ((a > c) == up) { keys[i] = c; keys[ixj] = a; }
                }
            }
            __syncthreads();
        }
    }
    for (int t = tid; t < TOPK; t += 256) {
        int j = 511 - (int)(keys[410 + t] & 0xFFFFFFFFull);
        atomicOr(&bw[j >> 5], 1u << (j & 31));
    }
    __syncthreads();
    if (tid < 16) g_adjbits[row*16 + tid] = bw[tid];
}

// ---------------- 2) BFS ----------------
__global__ void bfs_kernel()
{
    __shared__ unsigned int vis[16], fro[16], nxt[16];
    __shared__ int anyn;
    const int src = blockIdx.x;
    const int b   = src >> 9;
    const int s   = src & 511;
    const int tid = threadIdx.x;
    const size_t base = (size_t)src * Nn;

    g_spd[base + tid] = (tid == s) ? (unsigned char)1 : (unsigned char)0;
    if (tid < 16) {
        unsigned int m = (tid == (s >> 5)) ? (1u << (s & 31)) : 0u;
        vis[tid] = m; fro[tid] = m;
    }
    __syncthreads();

    for (int level = 1; level <= 10; level++) {
        if (tid < 16) nxt[tid] = 0u;
        if (tid == 0) anyn = 0;
        __syncthreads();

        bool active = (fro[tid >> 5] >> (tid & 31)) & 1u;
        #pragma unroll
        for (int w = 0; w < 16; w++) {
            unsigned int v = active ? g_adjbits[((size_t)(b*Nn) + tid)*16 + w] : 0u;
            unsigned int agg = __reduce_or_sync(0xFFFFFFFFu, v);
            if ((tid & 31) == 0 && agg) atomicOr(&nxt[w], agg);
        }
        __syncthreads();

        if (tid < 16) {
            unsigned int nv = nxt[tid] & ~vis[tid];
            nxt[tid] = nv;
            vis[tid] |= nv;
            if (nv) anyn = 1;
        }
        __syncthreads();
        if (!anyn) break;

        if ((nxt[tid >> 5] >> (tid & 31)) & 1u) {
            int idx = level + 1; if (idx > 6) idx = 6;
            g_spd[base + tid] = (unsigned char)idx;
        }
        if (tid < 16) fro[tid] = nxt[tid];
        __syncthreads();
    }
}

// ---------------- 3) pipelined split-bf16 wmma GEMM ---------------------------------
// C = A@W^T + bias (+res)(relu); 3-term split as one virtual-K GEMM.
// Tile 128x128, k-chunk 32, triple-buffered cp.async. 8 warps = 2x4.
// smem: 3 buffers x (A 128x40 bf16 + W 128x40 bf16) = 61440 B; epi reuses buffer 0.
#define GEMM_SMEM2 61440
__global__ void __launch_bounds__(256, 2) gemm2(
    const __nv_bfloat16* __restrict__ Ah, const __nv_bfloat16* __restrict__ Al,
    const __nv_bfloat16* __restrict__ Wh, const __nv_bfloat16* __restrict__ Wl,
    const float* __restrict__ bias, const float* __restrict__ res,
    float* __restrict__ Cf, __nv_bfloat16* __restrict__ Ch, __nv_bfloat16* __restrict__ Cl,
    int K, int Ndim, int relu)
{
    extern __shared__ __align__(128) char s[];
    const int tid = threadIdx.x, wid = tid >> 5, lane = tid & 31;
    const int m0 = blockIdx.y * 128, n0 = blockIdx.x * 128;
    const int wr = wid >> 2, wc = wid & 3;
    const int cpt = K >> 5;          // chunks per term
    const int nc = 3 * cpt;
    const int r = tid & 127, half = tid >> 7;
    const uint32_t sbase = smem_to_u32(s);

    wmma::fragment<wmma::accumulator,16,16,16,float> acc[4][2];
    #pragma unroll
    for (int rt = 0; rt < 4; rt++)
        #pragma unroll
        for (int ct = 0; ct < 2; ct++) wmma::fill_fragment(acc[rt][ct], 0.f);

    // stage chunk c into buffer buf
    auto stage = [&](int c, int buf) {
        int t = c / cpt;
        int kk = (c - t*cpt) << 5;
        const __nv_bfloat16* Ase = (t == 1) ? Al : Ah;
        const __nv_bfloat16* Wse = (t == 2) ? Wl : Wh;
        const __nv_bfloat16* ga = Ase + (size_t)(m0 + r)*K + kk + half*16;
        const __nv_bfloat16* gw = Wse + (size_t)(n0 + r)*K + kk + half*16;
        uint32_t sa = sbase + buf*20480 +         (r*40 + half*16)*2;
        uint32_t sw = sbase + buf*20480 + 10240 + (r*40 + half*16)*2;
        cpasync16(sa,      ga);
        cpasync16(sa + 16, ga + 8);
        cpasync16(sw,      gw);
        cpasync16(sw + 16, gw + 8);
        asm volatile("cp.async.commit_group;" ::: "memory");
    };

    stage(0, 0);
    stage(1, 1);

    for (int c = 0; c < nc; c++) {
        __syncthreads();                       // all warps done reading buf (c+2)%3 (as chunk c-1)
        if (c + 2 < nc) stage(c + 2, (c + 2) % 3);
        if (c + 2 < nc)       asm volatile("cp.async.wait_group 2;" ::: "memory");
        else if (c + 1 < nc)  asm volatile("cp.async.wait_group 1;" ::: "memory");
        else                  asm volatile("cp.async.wait_group 0;" ::: "memory");
        __syncthreads();                       // chunk c visible to all

        const __nv_bfloat16* As = (const __nv_bfloat16*)(s + (c % 3)*20480);
        const __nv_bfloat16* Ws = (const __nv_bfloat16*)(s + (c % 3)*20480 + 10240);
        #pragma unroll
        for (int ks = 0; ks < 2; ks++) {
            wmma::fragment<wmma::matrix_a,16,16,16,__nv_bfloat16,wmma::row_major> af[4];
            wmma::fragment<wmma::matrix_b,16,16,16,__nv_bfloat16,wmma::col_major> bf[2];
            #pragma unroll
            for (int rt = 0; rt < 4; rt++)
                wmma::load_matrix_sync(af[rt], As + (wr*64 + rt*16)*40 + ks*16, 40);
            #pragma unroll
            for (int ct = 0; ct < 2; ct++)
                wmma::load_matrix_sync(bf[ct], Ws + (wc*32 + ct*16)*40 + ks*16, 40);
            #pragma unroll
            for (int rt = 0; rt < 4; rt++)
                #pragma unroll
                for (int ct = 0; ct < 2; ct++)
                    wmma::mma_sync(acc[rt][ct], af[rt], bf[ct], acc[rt][ct]);
        }
    }
    __syncthreads();

    // epilogue: stage accs through smem (reuse buffers), fused bias/res/relu/split
    float* ep = (float*)s + wid*16*40;
    const int rr = lane & 15, hf = lane >> 4;
    #pragma unroll
    for (int rt = 0; rt < 4; rt++) {
        wmma::store_matrix_sync(ep,      acc[rt][0], 40, wmma::mem_row_major);
        wmma::store_matrix_sync(ep + 16, acc[rt][1], 40, wmma::mem_row_major);
        __syncwarp();
        const int m = m0 + wr*64 + rt*16 + rr;
        #pragma unroll
        for (int q = 0; q < 4; q++) {
            const int n = n0 + wc*32 + hf*16 + q*4;
            float4 v = *(float4*)&ep[rr*40 + hf*16 + q*4];
            float4 bv = *(const float4*)&bias[n];
            v.x += bv.x; v.y += bv.y; v.z += bv.z; v.w += bv.w;
            if (res) {
                float4 rv = *(const float4*)&res[(size_t)m*Ndim + n];
                v.x += rv.x; v.y += rv.y; v.z += rv.z; v.w += rv.w;
            }
            if (relu) {
                v.x = fmaxf(v.x, 0.f); v.y = fmaxf(v.y, 0.f);
                v.z = fmaxf(v.z, 0.f); v.w = fmaxf(v.w, 0.f);
            }
            if (Cf) *(float4*)&Cf[(size_t)m*Ndim + n] = v;
            if (Ch) {
                __nv_bfloat162 h0, l0, h1, l1;
                split2(v.x, v.y, h0, l0);
                split2(v.z, v.w, h1, l1);
                *(__nv_bfloat162*)&Ch[(size_t)m*Ndim + n]     = h0;
                *(__nv_bfloat162*)&Ch[(size_t)m*Ndim + n + 2] = h1;
                *(__nv_bfloat162*)&Cl[(size_t)m*Ndim + n]     = l0;
                *(__nv_bfloat162*)&Cl[(size_t)m*Ndim + n + 2] = l1;
            }
        }
        __syncwarp();
    }
}

// ---------------- 4) fused masked attention: 32 queries/block, register-tiled -------
#define AT_SMEM 81056
__global__ void __launch_bounds__(256, 2) attn_kernel(const float* __restrict__ emb_spd)
{
    extern __shared__ __align__(16) char asmem[];
    float* scf        = (float*)asmem;                   // [32][512]
    float* kvf        = (float*)(asmem + 65536);         // [32][68]
    float* qtf        = (float*)(asmem + 74240);         // [32][36]
    unsigned int* adjs = (unsigned int*)(asmem + 78848); // [32][16]
    float* embs       = (float*)(asmem + 80896);
    float* rinv       = (float*)(asmem + 80928);

    const int tid = threadIdx.x;                 // 256
    const int lane = tid & 31, w8 = tid >> 5;    // 8 warps
    const int qt = blockIdx.x, h = blockIdx.y, b = blockIdx.z;
    const int q0 = qt * 32;
    const float scale = 0.17677669529663687f;    // 1/sqrt(32)

    #pragma unroll
    for (int p = 0; p < 4; p++) {
        int i = w8 + p*8;
        qtf[lane*36 + i] = g_qkv[(size_t)(b*Nn + q0 + i)*768 + h*32 + lane];
    }
    for (int idx = tid; idx < 512; idx += 256) {
        int r = idx >> 4, w = idx & 15;
        adjs[idx] = g_adjbits[((size_t)(b*Nn) + q0 + r)*16 + w];
    }
    if (tid < 7) embs[tid] = emb_spd[tid*Hh + h];
    __syncthreads();

    // ---- scores ----
    const int qg = tid >> 4, jg = tid & 15;
    for (int jc = 0; jc < 8; jc++) {
        const int j0 = jc * 64;
        #pragma unroll
        for (int p = 0; p < 8; p++) {
            int j = w8 + p*8;
            kvf[lane*68 + j] = g_qkv[(size_t)(b*Nn + j0 + j)*768 + 256 + h*32 + lane];
        }
        __syncthreads();

        float4 a0 = {0,0,0,0}, a1 = {0,0,0,0};
        #pragma unroll
        for (int d = 0; d < 32; d++) {
            float2 q2 = *(float2*)&qtf[d*36 + qg*2];
            float4 k4 = *(float4*)&kvf[d*68 + jg*4];
            a0.x += q2.x*k4.x; a0.y += q2.x*k4.y; a0.z += q2.x*k4.z; a0.w += q2.x*k4.w;
            a1.x += q2.y*k4.x; a1.y += q2.y*k4.y; a1.z += q2.y*k4.z; a1.w += q2.y*k4.w;
        }
        const int jb = j0 + jg*4;
        #pragma unroll
        for (int qq = 0; qq < 2; qq++) {
            const int i = qg*2 + qq;
            float4 a = qq ? a1 : a0;
            unsigned int spw = *(const unsigned int*)&g_spd[(size_t)(b*Nn + q0 + i)*Nn + jb];
            unsigned int aw = adjs[i*16 + (jb >> 5)] >> (jb & 31);
            float4 o;
            o.x = (aw & 1u)      ? a.x*scale + embs[ spw        & 255u] : -INFINITY;
            o.y = ((aw>>1) & 1u) ? a.y*scale + embs[(spw >> 8)  & 255u] : -INFINITY;
            o.z = ((aw>>2) & 1u) ? a.z*scale + embs[(spw >> 16) & 255u] : -INFINITY;
            o.w = ((aw>>3) & 1u) ? a.w*scale + embs[(spw >> 24) & 255u] : -INFINITY;
            *(float4*)&scf[i*512 + jb] = o;
        }
        __syncthreads();
    }

    // ---- softmax ----
    #pragma unroll
    for (int rr = 0; rr < 4; rr++) {
        const int r = w8*4 + rr;
        float m = -INFINITY;
        for (int j = lane; j < 512; j += 32) m = fmaxf(m, scf[r*512 + j]);
        #pragma unroll
        for (int o = 16; o; o >>= 1) m = fmaxf(m, __shfl_xor_sync(0xFFFFFFFFu, m, o));
        float e = 0.f;
        for (int j = lane; j < 512; j += 32) {
            float s = scf[r*512 + j];
            float p = (s == -INFINITY) ? 0.f : __expf(s - m);
            scf[r*512 + j] = p;
            e += p;
        }
        #pragma unroll
        for (int o = 16; o; o >>= 1) e += __shfl_xor_sync(0xFFFFFFFFu, e, o);
        if (lane == 0) rinv[r] = 1.f / e;
    }
    __syncthreads();

    // ---- AV ----
    float o0 = 0.f, o1 = 0.f, o2 = 0.f, o3 = 0.f;
    for (int jc = 0; jc < 8; jc++) {
        const int j0 = jc * 64;
        #pragma unroll
        for (int p = 0; p < 8; p++) {
            int j = w8 + p*8;
            kvf[lane*68 + j] = g_qkv[(size_t)(b*Nn + j0 + j)*768 + 512 + h*32 + lane];
        }
        __syncthreads();
        #pragma unroll
        for (int jq = 0; jq < 16; jq++) {
            float4 vv = *(float4*)&kvf[lane*68 + jq*4];
            float4 s0 = *(float4*)&scf[(w8*4+0)*512 + j0 + jq*4];
            float4 s1 = *(float4*)&scf[(w8*4+1)*512 + j0 + jq*4];
            float4 s2 = *(float4*)&scf[(w8*4+2)*512 + j0 + jq*4];
            float4 s3 = *(float4*)&scf[(w8*4+3)*512 + j0 + jq*4];
            o0 += s0.x*vv.x + s0.y*vv.y + s0.z*vv.z + s0.w*vv.w;
            o1 += s1.x*vv.x + s1.y*vv.y + s1.z*vv.z + s1.w*vv.w;
            o2 += s2.x*vv.x + s2.y*vv.y + s2.z*vv.z + s2.w*vv.w;
            o3 += s3.x*vv.x + s3.y*vv.y + s3.z*vv.z + s3.w*vv.w;
        }
        __syncthreads();
    }
    {
        const int d = lane;
        #pragma unroll
        for (int rr = 0; rr < 4; rr++) {
            float v = (rr==0?o0:rr==1?o1:rr==2?o2:o3) * rinv[w8*4+rr];
            __nv_bfloat16 hh = __float2bfloat16(v);
            size_t idx = (size_t)(b*Nn + q0 + w8*4 + rr)*Ee + h*32 + d;
            g_ctxh[idx] = hh;
            g_ctxl[idx] = __float2bfloat16(v - __bfloat162float(hh));
        }
    }
}

// ---------------- 5) LayerNorm (+ optional split output) ----------------
__global__ void ln_kernel(const float* __restrict__ in, const float* __restrict__ g,
                          const float* __restrict__ be, float* __restrict__ out,
                          __nv_bfloat16* __restrict__ oh, __nv_bfloat16* __restrict__ ol)
{
    __shared__ float red[16];
    const int row = blockIdx.x, tid = threadIdx.x;
    float v = in[(size_t)row*Ee + tid];
    float s = v, sq = v*v;
    #pragma unroll
    for (int o = 16; o; o >>= 1) {
        s  += __shfl_xor_sync(0xFFFFFFFFu, s,  o);
        sq += __shfl_xor_sync(0xFFFFFFFFu, sq, o);
    }
    int wid = tid >> 5, lane = tid & 31;
    if (lane == 0) { red[wid] = s; red[8 + wid] = sq; }
    __syncthreads();
    if (tid == 0) {
        float ts = 0.f, tq = 0.f;
        #pragma unroll
        for (int w = 0; w < 8; w++) { ts += red[w]; tq += red[8 + w]; }
        red[0] = ts; red[8] = tq;
    }
    __syncthreads();
    float mean = red[0] * (1.f/Ee);
    float var  = red[8] * (1.f/Ee) - mean*mean;
    float rstd = rsqrtf(var + 1e-5f);
    float o = (v - mean) * rstd * g[tid] + be[tid];
    out[(size_t)row*Ee + tid] = o;
    if (oh) {
        __nv_bfloat16 hh = __float2bfloat16(o);
        oh[(size_t)row*Ee + tid] = hh;
        ol[(size_t)row*Ee + tid] = __float2bfloat16(o - __bfloat162float(hh));
    }
}

// ---------------- 6) attention pooling ----------------
__global__ void pool_kernel(const float* __restrict__ w_pool, const float* __restrict__ b_pool,
                            float* __restrict__ out)
{
    __shared__ float sc[512];
    __shared__ float red[16];
    __shared__ float bc[2];
    const int b = blockIdx.x, tid = threadIdx.x;
    const float* row = &g_x2[(size_t)(b*Nn + tid)*Ee];

    float dot = b_pool[0];
    #pragma unroll 8
    for (int e = 0; e < Ee; e++) dot += row[e] * w_pool[e];
    float t = tanhf(dot);
    sc[tid] = t;

    int wid = tid >> 5, lane = tid & 31;
    float m = t;
    #pragma unroll
    for (int o = 16; o; o >>= 1) m = fmaxf(m, __shfl_xor_sync(0xFFFFFFFFu, m, o));
    if (lane == 0) red[wid] = m;
    __syncthreads();
    if (tid == 0) {
        float mm = -INFINITY;
        #pragma unroll
        for (int w = 0; w < 16; w++) mm = fmaxf(mm, red[w]);
        bc[0] = mm;
    }
    __syncthreads();
    float p = __expf(t - bc[0]);
    sc[tid] = p;
    float s = p;
    #pragma unroll
    for (int o = 16; o; o >>= 1) s += __shfl_xor_sync(0xFFFFFFFFu, s, o);
    if (lane == 0) red[wid] = s;
    __syncthreads();
    if (tid == 0) {
        float ss = 0.f;
        #pragma unroll
        for (int w = 0; w < 16; w++) ss += red[w];
        bc[1] = ss;
    }
    __syncthreads();

    if (tid < Ee) {
        float acc = 0.f;
        float inv = 1.f / bc[1];
        for (int n = 0; n < Nn; n++)
            acc += g_x2[(size_t)(b*Nn + n)*Ee + tid] * sc[n];
        out[(size_t)b*Ee + tid] = acc * inv;
    }
}

// ---------------- launch ----------------
extern "C" void kernel_launch(void* const* d_in, const int* in_sizes, int n_in,
                              void* d_out, int out_size)
{
    const float* x       = (const float*)d_in[0];
    const float* adj     = (const float*)d_in[1];
    const float* emb_spd = (const float*)d_in[2];
    const float* w_qkv   = (const float*)d_in[3];
    const float* b_qkv   = (const float*)d_in[4];
    const float* w_out   = (const float*)d_in[5];
    const float* b_out   = (const float*)d_in[6];
    const float* w_ff1   = (const float*)d_in[7];
    const float* b_ff1   = (const float*)d_in[8];
    const float* w_ff2   = (const float*)d_in[9];
    const float* b_ff2   = (const float*)d_in[10];
    const float* g1      = (const float*)d_in[11];
    const float* beta1   = (const float*)d_in[12];
    const float* g2      = (const float*)d_in[13];
    const float* beta2   = (const float*)d_in[14];
    const float* w_pool  = (const float*)d_in[15];
    const float* b_pool  = (const float*)d_in[16];
    float* out = (float*)d_out;

    float* p_qkv; cudaGetSymbolAddress((void**)&p_qkv, g_qkv);
    float* p_y;   cudaGetSymbolAddress((void**)&p_y,   g_y);
    float* p_x1;  cudaGetSymbolAddress((void**)&p_x1,  g_x1);
    float* p_x2;  cudaGetSymbolAddress((void**)&p_x2,  g_x2);

    __nv_bfloat16 *xh, *xl, *ctxh, *ctxl, *x1h, *x1l, *ffh, *ffl;
    __nv_bfloat16 *wqkvh, *wqkvl, *wouth, *woutl, *wff1h, *wff1l, *wff2h, *wff2l;
    cudaGetSymbolAddress((void**)&xh, g_xh);     cudaGetSymbolAddress((void**)&xl, g_xl);
    cudaGetSymbolAddress((void**)&ctxh, g_ctxh); cudaGetSymbolAddress((void**)&ctxl, g_ctxl);
    cudaGetSymbolAddress((void**)&x1h, g_x1h);   cudaGetSymbolAddress((void**)&x1l, g_x1l);
    cudaGetSymbolAddress((void**)&ffh, g_ffh);   cudaGetSymbolAddress((void**)&ffl, g_ffl);
    cudaGetSymbolAddress((void**)&wqkvh, g_wqkvh); cudaGetSymbolAddress((void**)&wqkvl, g_wqkvl);
    cudaGetSymbolAddress((void**)&wouth, g_wouth); cudaGetSymbolAddress((void**)&woutl, g_woutl);
    cudaGetSymbolAddress((void**)&wff1h, g_wff1h); cudaGetSymbolAddress((void**)&wff1l, g_wff1l);
    cudaGetSymbolAddress((void**)&wff2h, g_wff2h); cudaGetSymbolAddress((void**)&wff2l, g_wff2l);

    cudaFuncSetAttribute(gemm2,       cudaFuncAttributeMaxDynamicSharedMemorySize, GEMM_SMEM2);
    cudaFuncSetAttribute(attn_kernel, cudaFuncAttributeMaxDynamicSharedMemorySize, AT_SMEM);

    // 0: fused operand conversion
    cvt_all<<<1792, 256>>>(x, w_qkv, w_out, w_ff1, w_ff2);
    // 1-2: graph topology
    topk_kernel<<<Bb*Nn, 256>>>(adj);
    bfs_kernel<<<Bb*Nn, 512>>>();
    // 3: QKV projection
    gemm2<<<dim3(6, 32), 256, GEMM_SMEM2>>>(xh, xl, wqkvh, wqkvl, b_qkv, nullptr,
                                            p_qkv, nullptr, nullptr, 256, 768, 0);
    // 4: attention (writes ctx h/l)
    attn_kernel<<<dim3(16, 8, 8), 256, AT_SMEM>>>(emb_spd);
    // 5: out projection + residual -> y fp32
    gemm2<<<dim3(2, 32), 256, GEMM_SMEM2>>>(ctxh, ctxl, wouth, woutl, b_out, x,
                                            p_y, nullptr, nullptr, 256, 256, 0);
    // 6: LN1 -> x1 fp32 + h/l
    ln_kernel<<<Mrows, 256>>>(p_y, g1, beta1, p_x1, x1h, x1l);
    // 7: FF1 + relu -> ff h/l only
    gemm2<<<dim3(8, 32), 256, GEMM_SMEM2>>>(x1h, x1l, wff1h, wff1l, b_ff1, nullptr,
                                            nullptr, ffh, ffl, 256, 1024, 1);
    // 8: FF2 + residual -> y fp32
    gemm2<<<dim3(2, 32), 256, GEMM_SMEM2>>>(ffh, ffl, wff2h, wff2l, b_ff2, p_x1,
                                            p_y, nullptr, nullptr, 1024, 256, 0);
    // 9: LN2 -> x2 fp32
    ln_kernel<<<Mrows, 256>>>(p_y, g2, beta2, p_x2, nullptr, nullptr);
    // 10: pooling
    pool_kernel<<<Bb, 512>>>(w_pool, b_pool, out);

    (void)in_sizes; (void)n_in; (void)out_size;
}

// round 5
// speedup vs baseline: 1.5897x; 1.5196x over previous
#include <cuda_runtime.h>
#include <cuda_bf16.h>
#include <mma.h>
#include <math.h>
#include <stdint.h>

using namespace nvcuda;

#define Bb 8
#define Nn 512
#define Ee 256
#define Hh 8
#define FFd 1024
#define TOPK 102
#define Mrows (Bb*Nn)   // 4096

// ---------------- device scratch ----------------
__device__ unsigned int  g_adjbits[Bb*Nn*16];
__device__ int           g_topkidx[Bb*Nn*104];
__device__ unsigned char g_spd[Bb*Nn*Nn];
__device__ float         g_score[Mrows];
__device__ __align__(16) float g_qkv[Mrows*768];
__device__ __align__(16) float g_y  [Mrows*Ee];
__device__ __align__(16) float g_x1 [Mrows*Ee];
__device__ __align__(16) float g_x2 [Mrows*Ee];

__device__ __align__(16) __nv_bfloat16 g_xh  [Mrows*Ee],  g_xl  [Mrows*Ee];
__device__ __align__(16) __nv_bfloat16 g_ctxh[Mrows*Ee],  g_ctxl[Mrows*Ee];
__device__ __align__(16) __nv_bfloat16 g_x1h [Mrows*Ee],  g_x1l [Mrows*Ee];
__device__ __align__(16) __nv_bfloat16 g_ffh [Mrows*FFd], g_ffl [Mrows*FFd];
__device__ __align__(16) __nv_bfloat16 g_wqkvh[768*256],  g_wqkvl[768*256];
__device__ __align__(16) __nv_bfloat16 g_wouth[256*256],  g_woutl[256*256];
__device__ __align__(16) __nv_bfloat16 g_wff1h[1024*256], g_wff1l[1024*256];
__device__ __align__(16) __nv_bfloat16 g_wff2h[256*1024], g_wff2l[256*1024];

// ================= helpers =================
__device__ __forceinline__ uint32_t smem_to_u32(const void* p) {
    uint32_t a;
    asm("{ .reg .u64 t; cvta.to.shared.u64 t, %1; cvt.u32.u64 %0, t; }" : "=r"(a) : "l"(p));
    return a;
}
__device__ __forceinline__ void cpasync16(uint32_t sm, const void* g) {
    asm volatile("cp.async.cg.shared.global [%0], [%1], 16;" :: "r"(sm), "l"(g) : "memory");
}
__device__ __forceinline__ void split2(float a, float b, __nv_bfloat162& h, __nv_bfloat162& l) {
    h = __floats2bfloat162_rn(a, b);
    l = __floats2bfloat162_rn(a - __bfloat162float(h.x), b - __bfloat162float(h.y));
}

// ---------------- 0) fused fp32 -> (hi,lo) bf16 split --------------------------------
__global__ void cvt_all(const float* __restrict__ x, const float* __restrict__ wqkv,
                        const float* __restrict__ wout, const float* __restrict__ wff1,
                        const float* __restrict__ wff2)
{
    int gid = blockIdx.x*256 + threadIdx.x;       // float4 index, total 458752
    const float* in; __nv_bfloat16 *hi, *lo; int off;
    if      (gid < 262144) { in = x;    hi = g_xh;    lo = g_xl;    off = gid; }
    else if (gid < 311296) { in = wqkv; hi = g_wqkvh; lo = g_wqkvl; off = gid - 262144; }
    else if (gid < 327680) { in = wout; hi = g_wouth; lo = g_woutl; off = gid - 311296; }
    else if (gid < 393216) { in = wff1; hi = g_wff1h; lo = g_wff1l; off = gid - 327680; }
    else                   { in = wff2; hi = g_wff2h; lo = g_wff2l; off = gid - 393216; }
    float4 v = ((const float4*)in)[off];
    __nv_bfloat162 h0, l0, h1, l1;
    split2(v.x, v.y, h0, l0);
    split2(v.z, v.w, h1, l1);
    int i = off*4;
    *(__nv_bfloat162*)(hi + i)     = h0;
    *(__nv_bfloat162*)(hi + i + 2) = h1;
    *(__nv_bfloat162*)(lo + i)     = l0;
    *(__nv_bfloat162*)(lo + i + 2) = l1;
}

// ---------------- 1) top-k -> adjacency bitset + index list --------------------------
__global__ void topk_kernel(const float* __restrict__ adj)
{
    __shared__ unsigned long long keys[512];
    __shared__ unsigned int bw[16];
    const int row = blockIdx.x;
    const int tid = threadIdx.x;

    for (int j = tid; j < 512; j += 256) {
        unsigned int bits = __float_as_uint(adj[(size_t)row*512 + j]);
        unsigned int ord  = bits ^ ((bits & 0x80000000u) ? 0xFFFFFFFFu : 0x80000000u);
        keys[j] = ((unsigned long long)ord << 32) | (unsigned long long)(511 - j);
    }
    if (tid < 16) bw[tid] = 0u;
    __syncthreads();

    for (int k = 2; k <= 512; k <<= 1) {
        for (int jj = k >> 1; jj > 0; jj >>= 1) {
            for (int i = tid; i < 512; i += 256) {
                int ixj = i ^ jj;
                if (ixj > i) {
                    unsigned long long a = keys[i], c = keys[ixj];
                    bool up = ((i & k) == 0);
                    if ((a > c) == up) { keys[i] = c; keys[ixj] = a; }
                }
            }
            __syncthreads();
        }
    }
    for (int t = tid; t < TOPK; t += 256) {
        int j = 511 - (int)(keys[410 + t] & 0xFFFFFFFFull);
        atomicOr(&bw[j >> 5], 1u << (j & 31));
        g_topkidx[(size_t)row*104 + t] = j;
    }
    __syncthreads();
    if (tid < 16) g_adjbits[row*16 + tid] = bw[tid];
}

// ---------------- 2) BFS: 16 warps = 16 independent sources, smem adjacency ---------
__global__ void __launch_bounds__(512) bfs16_kernel()
{
    __shared__ unsigned int adjs[512*17];
    const int tid = threadIdx.x, lane = tid & 31, w = tid >> 5;
    const int blk = blockIdx.x;                 // 0..255
    const int b = blk >> 5;
    const int s0 = (blk & 31) << 4;

    #pragma unroll
    for (int k = 0; k < 16; k++)
        adjs[tid*17 + k] = g_adjbits[((size_t)(b*Nn) + tid)*16 + k];
    __syncthreads();

    const int src = s0 + w;
    const size_t spdbase = (size_t)(b*Nn + src) * Nn;

    // zero spd row, set self
    for (int i = lane; i < 128; i += 32)
        ((unsigned int*)(g_spd + spdbase))[i] = 0u;
    __syncwarp();
    if (lane == 0) g_spd[spdbase + src] = 1;

    // lanes 0..15 hold frontier/visited words
    unsigned int visw = 0u, frow = 0u;
    if (lane < 16) {
        frow = (lane == (src >> 5)) ? (1u << (src & 31)) : 0u;
        visw = frow;
    }

    for (int level = 1; level <= 10; level++) {
        unsigned int acc[16];
        #pragma unroll
        for (int k = 0; k < 16; k++) acc[k] = 0u;

        #pragma unroll 1
        for (int wd = 0; wd < 16; wd++) {
            unsigned int bits = __shfl_sync(0xFFFFFFFFu, frow, wd);
            if ((bits >> lane) & 1u) {
                const unsigned int* row = &adjs[(wd*32 + lane)*17];
                #pragma unroll
                for (int k = 0; k < 16; k++) acc[k] |= row[k];
            }
        }
        unsigned int nv = 0u;
        #pragma unroll
        for (int k = 0; k < 16; k++) {
            unsigned int full = __reduce_or_sync(0xFFFFFFFFu, acc[k]);
            if (lane == k) nv = full & ~visw;
        }
        if (lane < 16) { visw |= nv; frow = nv; } else frow = 0u;

        unsigned int any = __reduce_or_sync(0xFFFFFFFFu, (lane < 16) ? nv : 0u);
        if (!any) break;

        unsigned char dval = (unsigned char)((level + 1 < 6) ? level + 1 : 6);
        #pragma unroll 1
        for (int wd = 0; wd < 16; wd++) {
            unsigned int bits = __shfl_sync(0xFFFFFFFFu, frow, wd);
            if ((bits >> lane) & 1u)
                g_spd[spdbase + wd*32 + lane] = dval;
        }
    }
}

// ---------------- 3) templated pipelined split-bf16 wmma GEMM ------------------------
// One chunk stages Ah,Al,Wh,Wl (32 K) and runs all 3 split terms from it.
template<int BM, int BN, int WR, int WC>
__global__ void __launch_bounds__(WR*WC*32, 2) gemm_t(
    const __nv_bfloat16* __restrict__ Ah, const __nv_bfloat16* __restrict__ Al,
    const __nv_bfloat16* __restrict__ Wh, const __nv_bfloat16* __restrict__ Wl,
    const float* __restrict__ bias, const float* __restrict__ res,
    float* __restrict__ Cf, __nv_bfloat16* __restrict__ Ch, __nv_bfloat16* __restrict__ Cl,
    int K, int Ndim, int relu)
{
    constexpr int WARPS = WR*WC, THREADS = WARPS*32;
    constexpr int WM = BM/WR, WN = BN/WC, FR = WM/16, FC = WN/16;
    static_assert(WN == 32, "epilogue assumes WN==32");
    constexpr int AROWS = BM*40;            // elements per A tile (padded rows of 40)
    constexpr int WROWS = BN*40;
    constexpr int BUFB = (2*AROWS + 2*WROWS)*2;   // bytes per buffer
    constexpr int SLOTS = (2*BM + 2*BN)*2;        // 32B slots per chunk

    extern __shared__ __align__(128) char s[];
    const uint32_t sb = smem_to_u32(s);
    const int tid = threadIdx.x, wid = tid >> 5, lane = tid & 31;
    const int m0 = blockIdx.y * BM, n0 = blockIdx.x * BN;
    const int wr = wid / WC, wc = wid % WC;

    wmma::fragment<wmma::accumulator,16,16,16,float> acc[FR][FC];
    #pragma unroll
    for (int r = 0; r < FR; r++)
        #pragma unroll
        for (int t = 0; t < FC; t++) wmma::fill_fragment(acc[r][t], 0.f);

    auto stage = [&](int c, int buf) {
        const int kk = c * 32;
        #pragma unroll
        for (int sl = tid; sl < SLOTS; sl += THREADS) {
            int half = sl & 1, rowid = sl >> 1;
            const __nv_bfloat16* src; uint32_t dst;
            if (rowid < BM)              { src = Ah + (size_t)(m0 + rowid)*K;          dst = sb + buf*BUFB + rowid*80; }
            else if (rowid < 2*BM)       { int r2 = rowid - BM;
                                           src = Al + (size_t)(m0 + r2)*K;             dst = sb + buf*BUFB + AROWS*2 + r2*80; }
            else if (rowid < 2*BM + BN)  { int r2 = rowid - 2*BM;
                                           src = Wh + (size_t)(n0 + r2)*K;             dst = sb + buf*BUFB + AROWS*4 + r2*80; }
            else                         { int r2 = rowid - 2*BM - BN;
                                           src = Wl + (size_t)(n0 + r2)*K;             dst = sb + buf*BUFB + AROWS*4 + WROWS*2 + r2*80; }
            cpasync16(dst + half*32,      src + kk + half*16);
            cpasync16(dst + half*32 + 16, src + kk + half*16 + 8);
        }
        asm volatile("cp.async.commit_group;" ::: "memory");
    };

    const int nc = K >> 5;
    stage(0, 0);

    for (int c = 0; c < nc; c++) {
        __syncthreads();   // everyone done reading buffer (c+1)&1 from chunk c-1
        if (c + 1 < nc) { stage(c + 1, (c + 1) & 1);
                          asm volatile("cp.async.wait_group 1;" ::: "memory"); }
        else            { asm volatile("cp.async.wait_group 0;" ::: "memory"); }
        __syncthreads();   // chunk c visible

        const __nv_bfloat16* sAh = (const __nv_bfloat16*)(s + (c & 1)*BUFB);
        const __nv_bfloat16* sAl = sAh + AROWS;
        const __nv_bfloat16* sWh = sAl + AROWS;
        const __nv_bfloat16* sWl = sWh + WROWS;

        #pragma unroll
        for (int ks = 0; ks < 2; ks++) {
            wmma::fragment<wmma::matrix_a,16,16,16,__nv_bfloat16,wmma::row_major> af[FR];
            wmma::fragment<wmma::matrix_b,16,16,16,__nv_bfloat16,wmma::col_major> bf_[FC];
            // term 1: Ah * Wh
            #pragma unroll
            for (int r = 0; r < FR; r++)
                wmma::load_matrix_sync(af[r], sAh + (wr*WM + r*16)*40 + ks*16, 40);
            #pragma unroll
            for (int t = 0; t < FC; t++)
                wmma::load_matrix_sync(bf_[t], sWh + (wc*WN + t*16)*40 + ks*16, 40);
            #pragma unroll
            for (int r = 0; r < FR; r++)
                #pragma unroll
                for (int t = 0; t < FC; t++) wmma::mma_sync(acc[r][t], af[r], bf_[t], acc[r][t]);
            // term 2: Ah * Wl (reuse af)
            #pragma unroll
            for (int t = 0; t < FC; t++)
                wmma::load_matrix_sync(bf_[t], sWl + (wc*WN + t*16)*40 + ks*16, 40);
            #pragma unroll
            for (int r = 0; r < FR; r++)
                #pragma unroll
                for (int t = 0; t < FC; t++) wmma::mma_sync(acc[r][t], af[r], bf_[t], acc[r][t]);
            // term 3: Al * Wh
            #pragma unroll
            for (int r = 0; r < FR; r++)
                wmma::load_matrix_sync(af[r], sAl + (wr*WM + r*16)*40 + ks*16, 40);
            #pragma unroll
            for (int t = 0; t < FC; t++)
                wmma::load_matrix_sync(bf_[t], sWh + (wc*WN + t*16)*40 + ks*16, 40);
            #pragma unroll
            for (int r = 0; r < FR; r++)
                #pragma unroll
                for (int t = 0; t < FC; t++) wmma::mma_sync(acc[r][t], af[r], bf_[t], acc[r][t]);
        }
    }
    __syncthreads();

    // epilogue (WN==32): stage through smem, fused bias/res/relu/split
    float* ep = (float*)s + wid*16*40;
    const int rr = lane & 15, hf = lane >> 4;
    #pragma unroll
    for (int rt = 0; rt < FR; rt++) {
        wmma::store_matrix_sync(ep,      acc[rt][0], 40, wmma::mem_row_major);
        wmma::store_matrix_sync(ep + 16, acc[rt][1], 40, wmma::mem_row_major);
        __syncwarp();
        const int m = m0 + wr*WM + rt*16 + rr;
        #pragma unroll
        for (int q = 0; q < 4; q++) {
            const int n = n0 + wc*WN + hf*16 + q*4;
            float4 v = *(float4*)&ep[rr*40 + hf*16 + q*4];
            float4 bv = *(const float4*)&bias[n];
            v.x += bv.x; v.y += bv.y; v.z += bv.z; v.w += bv.w;
            if (res) {
                float4 rv = *(const float4*)&res[(size_t)m*Ndim + n];
                v.x += rv.x; v.y += rv.y; v.z += rv.z; v.w += rv.w;
            }
            if (relu) {
                v.x = fmaxf(v.x, 0.f); v.y = fmaxf(v.y, 0.f);
                v.z = fmaxf(v.z, 0.f); v.w = fmaxf(v.w, 0.f);
            }
            if (Cf) *(float4*)&Cf[(size_t)m*Ndim + n] = v;
            if (Ch) {
                __nv_bfloat162 h0, l0, h1, l1;
                split2(v.x, v.y, h0, l0);
                split2(v.z, v.w, h1, l1);
                *(__nv_bfloat162*)&Ch[(size_t)m*Ndim + n]     = h0;
                *(__nv_bfloat162*)&Ch[(size_t)m*Ndim + n + 2] = h1;
                *(__nv_bfloat162*)&Cl[(size_t)m*Ndim + n]     = l0;
                *(__nv_bfloat162*)&Cl[(size_t)m*Ndim + n + 2] = l1;
            }
        }
        __syncwarp();
    }
}

// ---------------- 4) sparse masked attention: one warp per query row ----------------
__global__ void __launch_bounds__(256) attn_sparse(const float* __restrict__ emb_spd)
{
    __shared__ float sq[8][32];
    __shared__ float sp[8][104];
    __shared__ int   si[8][104];
    __shared__ float embs[8];

    const int tid = threadIdx.x, lane = tid & 31, w = tid >> 5;
    const int qt = blockIdx.x, h = blockIdx.y, b = blockIdx.z;
    const int q = qt*8 + w;
    const int row = b*Nn + q;
    const float scale = 0.17677669529663687f;    // 1/sqrt(32)

    if (tid < 7) embs[tid] = emb_spd[tid*Hh + h];
    sq[w][lane] = g_qkv[(size_t)row*768 + h*32 + lane];
    __syncthreads();

    float sc[4];
    int   jj[4];
    float mx = -INFINITY;
    #pragma unroll
    for (int r = 0; r < 4; r++) {
        const int t = lane + r*32;
        sc[r] = -INFINITY; jj[r] = 0;
        if (t < TOPK) {
            int j = g_topkidx[(size_t)row*104 + t];
            jj[r] = j;
            const float4* kp = (const float4*)&g_qkv[(size_t)(b*Nn + j)*768 + 256 + h*32];
            float dot = 0.f;
            #pragma unroll
            for (int g2 = 0; g2 < 8; g2++) {
                float4 k4 = kp[g2];
                dot += sq[w][g2*4+0]*k4.x + sq[w][g2*4+1]*k4.y
                     + sq[w][g2*4+2]*k4.z + sq[w][g2*4+3]*k4.w;
            }
            int spi = g_spd[(size_t)row*Nn + j];
            sc[r] = dot*scale + embs[spi];
            mx = fmaxf(mx, sc[r]);
        }
    }
    #pragma unroll
    for (int o = 16; o; o >>= 1) mx = fmaxf(mx, __shfl_xor_sync(0xFFFFFFFFu, mx, o));
    float e = 0.f;
    #pragma unroll
    for (int r = 0; r < 4; r++) {
        const int t = lane + r*32;
        if (t < TOPK) {
            float p = __expf(sc[r] - mx);
            e += p;
            sp[w][t] = p;
            si[w][t] = jj[r];
        }
    }
    #pragma unroll
    for (int o = 16; o; o >>= 1) e += __shfl_xor_sync(0xFFFFFFFFu, e, o);
    __syncwarp();

    float acc = 0.f;
    #pragma unroll 6
    for (int t = 0; t < TOPK; t++) {
        int j = si[w][t];
        acc += sp[w][t] * g_qkv[(size_t)(b*Nn + j)*768 + 512 + h*32 + lane];
    }
    float v = acc / e;
    __nv_bfloat16 hh = __float2bfloat16(v);
    size_t oidx = (size_t)row*Ee + h*32 + lane;
    g_ctxh[oidx] = hh;
    g_ctxl[oidx] = __float2bfloat16(v - __bfloat162float(hh));
}

// ---------------- 5) LayerNorm (+ optional split out, + optional pool score) --------
__global__ void ln_kernel(const float* __restrict__ in, const float* __restrict__ g,
                          const float* __restrict__ be, float* __restrict__ out,
                          __nv_bfloat16* __restrict__ oh, __nv_bfloat16* __restrict__ ol,
                          const float* __restrict__ wp, const float* __restrict__ bp,
                          float* __restrict__ scout)
{
    __shared__ float red[16];
    const int row = blockIdx.x, tid = threadIdx.x;
    float v = in[(size_t)row*Ee + tid];
    float s = v, sq = v*v;
    #pragma unroll
    for (int o = 16; o; o >>= 1) {
        s  += __shfl_xor_sync(0xFFFFFFFFu, s,  o);
        sq += __shfl_xor_sync(0xFFFFFFFFu, sq, o);
    }
    int wid = tid >> 5, lane = tid & 31;
    if (lane == 0) { red[wid] = s; red[8 + wid] = sq; }
    __syncthreads();
    if (tid == 0) {
        float ts = 0.f, tq = 0.f;
        #pragma unroll
        for (int w2 = 0; w2 < 8; w2++) { ts += red[w2]; tq += red[8 + w2]; }
        red[0] = ts; red[8] = tq;
    }
    __syncthreads();
    float mean = red[0] * (1.f/Ee);
    float var  = red[8] * (1.f/Ee) - mean*mean;
    float rstd = rsqrtf(var + 1e-5f);
    float ov = (v - mean) * rstd * g[tid] + be[tid];
    out[(size_t)row*Ee + tid] = ov;
    if (oh) {
        __nv_bfloat16 hh = __float2bfloat16(ov);
        oh[(size_t)row*Ee + tid] = hh;
        ol[(size_t)row*Ee + tid] = __float2bfloat16(ov - __bfloat162float(hh));
    }
    if (scout) {
        float d = ov * wp[tid];
        #pragma unroll
        for (int o = 16; o; o >>= 1) d += __shfl_xor_sync(0xFFFFFFFFu, d, o);
        __syncthreads();
        if (lane == 0) red[wid] = d;
        __syncthreads();
        if (tid == 0) {
            float t2 = 0.f;
            #pragma unroll
            for (int w2 = 0; w2 < 8; w2++) t2 += red[w2];
            scout[row] = tanhf(t2 + bp[0]);
        }
    }
}

// ---------------- 6) pooling: grid (batch, col-chunk) -------------------------------
__global__ void __launch_bounds__(256) pool2_kernel(float* __restrict__ out)
{
    __shared__ float p[512];
    __shared__ float red[8];
    __shared__ float part[8][32];
    __shared__ float Mv, Ev;
    const int b = blockIdx.x, cc = blockIdx.y;
    const int tid = threadIdx.x, lane = tid & 31, w = tid >> 5;

    float s0 = g_score[b*Nn + tid];
    float s1 = g_score[b*Nn + 256 + tid];
    float m = fmaxf(s0, s1);
    #pragma unroll
    for (int o = 16; o; o >>= 1) m = fmaxf(m, __shfl_xor_sync(0xFFFFFFFFu, m, o));
    if (lane == 0) red[w] = m;
    __syncthreads();
    if (tid == 0) {
        float mm = -INFINITY;
        #pragma unroll
        for (int i = 0; i < 8; i++) mm = fmaxf(mm, red[i]);
        Mv = mm;
    }
    __syncthreads();
    float p0 = __expf(s0 - Mv), p1 = __expf(s1 - Mv);
    p[tid] = p0; p[tid + 256] = p1;
    float e = p0 + p1;
    #pragma unroll
    for (int o = 16; o; o >>= 1) e += __shfl_xor_sync(0xFFFFFFFFu, e, o);
    if (lane == 0) red[w] = e;
    __syncthreads();
    if (tid == 0) {
        float t = 0.f;
        #pragma unroll
        for (int i = 0; i < 8; i++) t += red[i];
        Ev = t;
    }
    __syncthreads();

    const int col = cc*32 + lane;
    float acc = 0.f;
    #pragma unroll 4
    for (int i = 0; i < 64; i++) {
        int n = w*64 + i;
        acc += p[n] * g_x2[(size_t)(b*Nn + n)*Ee + col];
    }
    part[w][lane] = acc;
    __syncthreads();
    if (w == 0) {
        float a = 0.f;
        #pragma unroll
        for (int g2 = 0; g2 < 8; g2++) a += part[g2][lane];
        out[b*Ee + col] = a / Ev;
    }
}

// ---------------- launch ----------------
extern "C" void kernel_launch(void* const* d_in, const int* in_sizes, int n_in,
                              void* d_out, int out_size)
{
    const float* x       = (const float*)d_in[0];
    const float* adj     = (const float*)d_in[1];
    const float* emb_spd = (const float*)d_in[2];
    const float* w_qkv   = (const float*)d_in[3];
    const float* b_qkv   = (const float*)d_in[4];
    const float* w_out   = (const float*)d_in[5];
    const float* b_out   = (const float*)d_in[6];
    const float* w_ff1   = (const float*)d_in[7];
    const float* b_ff1   = (const float*)d_in[8];
    const float* w_ff2   = (const float*)d_in[9];
    const float* b_ff2   = (const float*)d_in[10];
    const float* g1      = (const float*)d_in[11];
    const float* beta1   = (const float*)d_in[12];
    const float* g2      = (const float*)d_in[13];
    const float* beta2   = (const float*)d_in[14];
    const float* w_pool  = (const float*)d_in[15];
    const float* b_pool  = (const float*)d_in[16];
    float* out = (float*)d_out;

    float *p_qkv, *p_y, *p_x1, *p_score;
    cudaGetSymbolAddress((void**)&p_qkv, g_qkv);
    cudaGetSymbolAddress((void**)&p_y,   g_y);
    cudaGetSymbolAddress((void**)&p_x1,  g_x1);
    cudaGetSymbolAddress((void**)&p_score, g_score);
    float* p_x2; cudaGetSymbolAddress((void**)&p_x2, g_x2);

    __nv_bfloat16 *xh, *xl, *ctxh, *ctxl, *x1h, *x1l, *ffh, *ffl;
    __nv_bfloat16 *wqkvh, *wqkvl, *wouth, *woutl, *wff1h, *wff1l, *wff2h, *wff2l;
    cudaGetSymbolAddress((void**)&xh, g_xh);     cudaGetSymbolAddress((void**)&xl, g_xl);
    cudaGetSymbolAddress((void**)&ctxh, g_ctxh); cudaGetSymbolAddress((void**)&ctxl, g_ctxl);
    cudaGetSymbolAddress((void**)&x1h, g_x1h);   cudaGetSymbolAddress((void**)&x1l, g_x1l);
    cudaGetSymbolAddress((void**)&ffh, g_ffh);   cudaGetSymbolAddress((void**)&ffl, g_ffl);
    cudaGetSymbolAddress((void**)&wqkvh, g_wqkvh); cudaGetSymbolAddress((void**)&wqkvl, g_wqkvl);
    cudaGetSymbolAddress((void**)&wouth, g_wouth); cudaGetSymbolAddress((void**)&woutl, g_woutl);
    cudaGetSymbolAddress((void**)&wff1h, g_wff1h); cudaGetSymbolAddress((void**)&wff1l, g_wff1l);
    cudaGetSymbolAddress((void**)&wff2h, g_wff2h); cudaGetSymbolAddress((void**)&wff2l, g_wff2l);

    auto kA = gemm_t<128,128,2,4>;   // 256 thr, smem 81920
    auto kB = gemm_t<64,64,2,2>;     // 128 thr, smem 40960
    cudaFuncSetAttribute(kA, cudaFuncAttributeMaxDynamicSharedMemorySize, 81920);
    cudaFuncSetAttribute(kB, cudaFuncAttributeMaxDynamicSharedMemorySize, 40960);

    cvt_all<<<1792, 256>>>(x, w_qkv, w_out, w_ff1, w_ff2);
    topk_kernel<<<Bb*Nn, 256>>>(adj);
    bfs16_kernel<<<256, 512>>>();
    // QKV: [4096,768] = x @ w_qkv^T
    kA<<<dim3(6, 32), 256, 81920>>>(xh, xl, wqkvh, wqkvl, b_qkv, nullptr,
                                    p_qkv, nullptr, nullptr, 256, 768, 0);
    attn_sparse<<<dim3(64, 8, 8), 256>>>(emb_spd);
    // out-proj + residual
    kB<<<dim3(4, 64), 128, 40960>>>(ctxh, ctxl, wouth, woutl, b_out, x,
                                    p_y, nullptr, nullptr, 256, 256, 0);
    ln_kernel<<<Mrows, 256>>>(p_y, g1, beta1, p_x1, x1h, x1l, nullptr, nullptr, nullptr);
    // FF1 + relu -> split only
    kA<<<dim3(8, 32), 256, 81920>>>(x1h, x1l, wff1h, wff1l, b_ff1, nullptr,
                                    nullptr, ffh, ffl, 256, 1024, 1);
    // FF2 + residual
    kB<<<dim3(4, 64), 128, 40960>>>(ffh, ffl, wff2h, wff2l, b_ff2, p_x1,
                                    p_y, nullptr, nullptr, 1024, 256, 0);
    // LN2 + fused pool score
    ln_kernel<<<Mrows, 256>>>(p_y, g2, beta2, p_x2, nullptr, nullptr,
                              w_pool, b_pool, p_score);
    pool2_kernel<<<dim3(8, 8), 256>>>(out);

    (void)in_sizes; (void)n_in; (void)out_size;
}